// round 1
// baseline (speedup 1.0000x reference)
#include <cuda_runtime.h>

#define Bb   2
#define Ls   2048
#define Hh   16
#define Dd   256
#define HD   4096   // H*D
#define KD   2048   // HKV*D
#define HIDd 2048
#define NB   8
#define BLK  256

// ---------------- scratch (static device memory; no allocs) ----------------
static __device__ __align__(128) float g_qpre[Bb * Ls * HD];   // q pre-conv; reused as sc later
static __device__ __align__(128) float g_q   [Bb * Ls * HD];   // q post conv+silu
static __device__ __align__(128) float g_kpre[Bb * Ls * KD];
static __device__ __align__(128) float g_k   [Bb * Ls * KD];
static __device__ __align__(128) float g_v   [Bb * Ls * KD];
static __device__ __align__(128) float g_kv  [Bb * Hh * NB * Dd * Dd]; // kvloc -> kvin (in-place prefix)
static __device__ __align__(128) float g_o   [Bb * Ls * HD];

// ---------------- big SGEMM: C[M,N] = A[M,K] @ B[K,N], row-major ----------------
// 128x128 tile, BK=8, 256 threads, 8x8 microtile.
__global__ __launch_bounds__(256) void sgemm_nn(const float* __restrict__ A,
                                                const float* __restrict__ B,
                                                float* __restrict__ C,
                                                int M, int N, int K)
{
    __shared__ float As[8][128];
    __shared__ float Bs[8][128];
    const int tid = threadIdx.x;
    const int m0 = blockIdx.y * 128, n0 = blockIdx.x * 128;
    const int ty = tid >> 4, tx = tid & 15;

    float acc[8][8];
#pragma unroll
    for (int i = 0; i < 8; i++)
#pragma unroll
        for (int j = 0; j < 8; j++) acc[i][j] = 0.f;

    const int aRow = tid >> 1, aC = (tid & 1) * 4;
    const int bRow = tid >> 5, bC = (tid & 31) * 4;
    const float* Ap = A + (size_t)(m0 + aRow) * K + aC;
    const float* Bp = B + (size_t)bRow * N + n0 + bC;

    for (int k0 = 0; k0 < K; k0 += 8) {
        float4 a = *(const float4*)(Ap + k0);
        float4 b = *(const float4*)(Bp + (size_t)k0 * N);
        As[aC + 0][aRow] = a.x;
        As[aC + 1][aRow] = a.y;
        As[aC + 2][aRow] = a.z;
        As[aC + 3][aRow] = a.w;
        *(float4*)&Bs[bRow][bC] = b;
        __syncthreads();
#pragma unroll
        for (int kk = 0; kk < 8; kk++) {
            float4 a0 = *(const float4*)&As[kk][ty * 8];
            float4 a1 = *(const float4*)&As[kk][ty * 8 + 4];
            float4 b0 = *(const float4*)&Bs[kk][tx * 8];
            float4 b1 = *(const float4*)&Bs[kk][tx * 8 + 4];
            float av[8] = {a0.x, a0.y, a0.z, a0.w, a1.x, a1.y, a1.z, a1.w};
            float bv[8] = {b0.x, b0.y, b0.z, b0.w, b1.x, b1.y, b1.z, b1.w};
#pragma unroll
            for (int i = 0; i < 8; i++)
#pragma unroll
                for (int j = 0; j < 8; j++) acc[i][j] += av[i] * bv[j];
        }
        __syncthreads();
    }
#pragma unroll
    for (int i = 0; i < 8; i++) {
        float* Cp = C + (size_t)(m0 + ty * 8 + i) * N + n0 + tx * 8;
        *(float4*)(Cp)     = make_float4(acc[i][0], acc[i][1], acc[i][2], acc[i][3]);
        *(float4*)(Cp + 4) = make_float4(acc[i][4], acc[i][5], acc[i][6], acc[i][7]);
    }
}

// ---------------- depthwise causal conv (K=4) + SiLU ----------------
// out[b,l,c] = silu(bias[c] + sum_t w[c,t] * in[b, l+t-3, c])
__global__ __launch_bounds__(256) void conv_silu(const float* __restrict__ in,
                                                 const float* __restrict__ w,
                                                 const float* __restrict__ bias,
                                                 float* __restrict__ out,
                                                 int C, int total)
{
    int i = blockIdx.x * blockDim.x + threadIdx.x;
    if (i >= total) return;
    int c = i % C;
    int l = (i / C) % Ls;
    float acc = bias[c];
#pragma unroll
    for (int t = 0; t < 4; t++) {
        int ls = l + t - 3;
        if (ls >= 0) acc += w[c * 4 + t] * in[i + (t - 3) * C];
    }
    out[i] = acc / (1.f + expf(-acc));
}

// ---------------- local KV per (b,h,chunk): kv[d,e] = sum_n kdec(n)*k[n,d]*v[n,e] ----------------
__global__ __launch_bounds__(256) void kvloc_kernel(const float* __restrict__ slope)
{
    const int z = blockIdx.z;
    const int b = z / (Hh * NB);
    const int h = (z / NB) % Hh;
    const int c = z % NB;
    const int kvh = h >> 1;                 // GQA: rep=2
    const float s = slope[h];

    const float* kb = g_k + (size_t)(b * Ls + c * BLK) * KD + kvh * Dd;
    const float* vb = g_v + (size_t)(b * Ls + c * BLK) * KD + kvh * Dd;
    const int d0 = blockIdx.y * 64, e0 = blockIdx.x * 64;

    __shared__ float As[16][64];
    __shared__ float Bs[16][64];
    const int tid = threadIdx.x;
    const int ty = tid >> 4, tx = tid & 15;
    const int nl = tid >> 4;                // row 0..15
    const int cq = (tid & 15) * 4;          // col 0..60

    float acc[4][4] = {};
    for (int n0 = 0; n0 < BLK; n0 += 16) {
        const int n = n0 + nl;
        const float kd = expf(-s * (float)(BLK - 1 - n));
        float4 a  = *(const float4*)(kb + (size_t)n * KD + d0 + cq);
        float4 bb = *(const float4*)(vb + (size_t)n * KD + e0 + cq);
        As[nl][cq + 0] = kd * a.x;
        As[nl][cq + 1] = kd * a.y;
        As[nl][cq + 2] = kd * a.z;
        As[nl][cq + 3] = kd * a.w;
        *(float4*)&Bs[nl][cq] = bb;
        __syncthreads();
#pragma unroll
        for (int kk = 0; kk < 16; kk++) {
            float4 a4 = *(const float4*)&As[kk][ty * 4];
            float4 b4 = *(const float4*)&Bs[kk][tx * 4];
            float av[4] = {a4.x, a4.y, a4.z, a4.w};
            float bv[4] = {b4.x, b4.y, b4.z, b4.w};
#pragma unroll
            for (int i = 0; i < 4; i++)
#pragma unroll
                for (int j = 0; j < 4; j++) acc[i][j] += av[i] * bv[j];
        }
        __syncthreads();
    }
    float* outp = g_kv + (size_t)z * Dd * Dd;
#pragma unroll
    for (int i = 0; i < 4; i++) {
        float* op = outp + (size_t)(d0 + ty * 4 + i) * Dd + e0 + tx * 4;
        *(float4*)op = make_float4(acc[i][0], acc[i][1], acc[i][2], acc[i][3]);
    }
}

// ---------------- in-place exclusive decay prefix over chunks ----------------
__global__ __launch_bounds__(256) void kvprefix(const float* __restrict__ slope)
{
    const int idx = blockIdx.x * blockDim.x + threadIdx.x;   // exactly Bb*Hh*Dd*Dd threads
    const int bh = idx >> 16;
    const int de = idx & 65535;
    const int h = bh % Hh;
    const float bdec = expf(-slope[h] * (float)BLK);
    float acc = 0.f;
    float* p = g_kv + (size_t)bh * NB * 65536 + de;
#pragma unroll
    for (int c = 0; c < NB; c++) {
        float loc = p[(size_t)c * 65536];
        p[(size_t)c * 65536] = acc;          // kv entering chunk c
        acc = acc * bdec + loc;
    }
}

// ---------------- masked decayed scores: sc[m,n] = mask*decay * dot(q[m,:], k[n,:]) ----------------
__global__ __launch_bounds__(256) void sc_kernel(const float* __restrict__ slope)
{
    const int z = blockIdx.z;
    const int b = z / (Hh * NB);
    const int h = (z / NB) % Hh;
    const int c = z % NB;
    const int kvh = h >> 1;
    const float s = slope[h];

    const float* qb = g_q + (size_t)(b * Ls + c * BLK) * HD + h * Dd;
    const float* kb = g_k + (size_t)(b * Ls + c * BLK) * KD + kvh * Dd;
    const int m0 = blockIdx.y * 64, n0 = blockIdx.x * 64;

    __shared__ float As[16][64];
    __shared__ float Bs[16][64];
    const int tid = threadIdx.x;
    const int ty = tid >> 4, tx = tid & 15;
    const int rl = tid >> 2;               // row 0..63
    const int dq = (tid & 3) * 4;          // k-col 0..12

    float acc[4][4] = {};
    for (int dd = 0; dd < Dd; dd += 16) {
        float4 a  = *(const float4*)(qb + (size_t)(m0 + rl) * HD + dd + dq);
        float4 bb = *(const float4*)(kb + (size_t)(n0 + rl) * KD + dd + dq);
        As[dq + 0][rl] = a.x;  As[dq + 1][rl] = a.y;
        As[dq + 2][rl] = a.z;  As[dq + 3][rl] = a.w;
        Bs[dq + 0][rl] = bb.x; Bs[dq + 1][rl] = bb.y;
        Bs[dq + 2][rl] = bb.z; Bs[dq + 3][rl] = bb.w;
        __syncthreads();
#pragma unroll
        for (int kk = 0; kk < 16; kk++) {
            float4 a4 = *(const float4*)&As[kk][ty * 4];
            float4 b4 = *(const float4*)&Bs[kk][tx * 4];
            float av[4] = {a4.x, a4.y, a4.z, a4.w};
            float bv[4] = {b4.x, b4.y, b4.z, b4.w};
#pragma unroll
            for (int i = 0; i < 4; i++)
#pragma unroll
                for (int j = 0; j < 4; j++) acc[i][j] += av[i] * bv[j];
        }
        __syncthreads();
    }
    float* scp = g_qpre + (size_t)z * 65536;   // reuse q-pre buffer as sc
#pragma unroll
    for (int i = 0; i < 4; i++)
#pragma unroll
        for (int j = 0; j < 4; j++) {
            int m = m0 + ty * 4 + i, n = n0 + tx * 4 + j;
            float v = (m >= n) ? acc[i][j] * expf(-s * (float)(m - n)) : 0.f;
            scp[(size_t)m * BLK + n] = v;
        }
}

// ---------------- output: o = (q*qdec) @ kv_in + sc @ v ----------------
__global__ __launch_bounds__(256) void out_kernel(const float* __restrict__ slope)
{
    const int z = blockIdx.z;
    const int b = z / (Hh * NB);
    const int h = (z / NB) % Hh;
    const int c = z % NB;
    const int kvh = h >> 1;
    const float s = slope[h];

    const float* qb  = g_q    + (size_t)(b * Ls + c * BLK) * HD + h * Dd;
    const float* vb  = g_v    + (size_t)(b * Ls + c * BLK) * KD + kvh * Dd;
    const float* kvp = g_kv   + (size_t)z * 65536;   // kv entering this chunk
    const float* scp = g_qpre + (size_t)z * 65536;
    const int m0 = blockIdx.y * 64, e0 = blockIdx.x * 64;

    __shared__ float As[16][64];
    __shared__ float Bs[16][64];
    const int tid = threadIdx.x;
    const int ty = tid >> 4, tx = tid & 15;
    const int rl  = tid >> 2;              // for transposed A loads
    const int dq  = (tid & 3) * 4;
    const int rl2 = tid >> 4;              // for direct B loads
    const int eq  = (tid & 15) * 4;

    float acc[4][4] = {};

    // phase 1: inter-chunk, sum over d
    for (int dd = 0; dd < Dd; dd += 16) {
        const int m = m0 + rl;
        const float qdec = expf(-s * (float)(m + 1));
        float4 a = *(const float4*)(qb + (size_t)m * HD + dd + dq);
        As[dq + 0][rl] = qdec * a.x;
        As[dq + 1][rl] = qdec * a.y;
        As[dq + 2][rl] = qdec * a.z;
        As[dq + 3][rl] = qdec * a.w;
        float4 bb = *(const float4*)(kvp + (size_t)(dd + rl2) * Dd + e0 + eq);
        *(float4*)&Bs[rl2][eq] = bb;
        __syncthreads();
#pragma unroll
        for (int kk = 0; kk < 16; kk++) {
            float4 a4 = *(const float4*)&As[kk][ty * 4];
            float4 b4 = *(const float4*)&Bs[kk][tx * 4];
            float av[4] = {a4.x, a4.y, a4.z, a4.w};
            float bv[4] = {b4.x, b4.y, b4.z, b4.w};
#pragma unroll
            for (int i = 0; i < 4; i++)
#pragma unroll
                for (int j = 0; j < 4; j++) acc[i][j] += av[i] * bv[j];
        }
        __syncthreads();
    }

    // phase 2: intra-chunk, sum over n
    for (int nn = 0; nn < BLK; nn += 16) {
        float4 a = *(const float4*)(scp + (size_t)(m0 + rl) * BLK + nn + dq);
        As[dq + 0][rl] = a.x;  As[dq + 1][rl] = a.y;
        As[dq + 2][rl] = a.z;  As[dq + 3][rl] = a.w;
        float4 bb = *(const float4*)(vb + (size_t)(nn + rl2) * KD + e0 + eq);
        *(float4*)&Bs[rl2][eq] = bb;
        __syncthreads();
#pragma unroll
        for (int kk = 0; kk < 16; kk++) {
            float4 a4 = *(const float4*)&As[kk][ty * 4];
            float4 b4 = *(const float4*)&Bs[kk][tx * 4];
            float av[4] = {a4.x, a4.y, a4.z, a4.w};
            float bv[4] = {b4.x, b4.y, b4.z, b4.w};
#pragma unroll
            for (int i = 0; i < 4; i++)
#pragma unroll
                for (int j = 0; j < 4; j++) acc[i][j] += av[i] * bv[j];
        }
        __syncthreads();
    }

#pragma unroll
    for (int i = 0; i < 4; i++) {
        const int m = m0 + ty * 4 + i;
        float* op = g_o + (size_t)(b * Ls + c * BLK + m) * HD + h * Dd + e0 + tx * 4;
        *(float4*)op = make_float4(acc[i][0], acc[i][1], acc[i][2], acc[i][3]);
    }
}

// ---------------- SimpleRMSNorm over last dim (4096), in place ----------------
__global__ __launch_bounds__(256) void rmsnorm_kernel()
{
    const int row = blockIdx.x;
    float* p = g_o + (size_t)row * HD;
    const int tid = threadIdx.x;
    float ss = 0.f;
    for (int i = tid; i < HD; i += 256) {
        float v = p[i];
        ss += v * v;
    }
#pragma unroll
    for (int off = 16; off > 0; off >>= 1) ss += __shfl_xor_sync(0xffffffffu, ss, off);
    __shared__ float red[8];
    __shared__ float scale_s;
    if ((tid & 31) == 0) red[tid >> 5] = ss;
    __syncthreads();
    if (tid == 0) {
        float tot = 0.f;
#pragma unroll
        for (int w = 0; w < 8; w++) tot += red[w];
        scale_s = rsqrtf(tot / (float)HD + 1e-6f);
    }
    __syncthreads();
    const float sc = scale_s;
    for (int i = tid; i < HD; i += 256) p[i] *= sc;
}

// ---------------- launcher ----------------
extern "C" void kernel_launch(void* const* d_in, const int* in_sizes, int n_in,
                              void* d_out, int out_size)
{
    const float* x     = (const float*)d_in[0];
    const float* Wq    = (const float*)d_in[1];
    const float* Wk    = (const float*)d_in[2];
    const float* Wv    = (const float*)d_in[3];
    const float* Wo    = (const float*)d_in[4];
    const float* cqw   = (const float*)d_in[5];
    const float* cqb   = (const float*)d_in[6];
    const float* ckw   = (const float*)d_in[7];
    const float* ckb   = (const float*)d_in[8];
    const float* slope = (const float*)d_in[9];
    float* out = (float*)d_out;

    float *qpre, *q, *kpre, *k, *v, *kv, *o;
    cudaGetSymbolAddress((void**)&qpre, g_qpre);
    cudaGetSymbolAddress((void**)&q,    g_q);
    cudaGetSymbolAddress((void**)&kpre, g_kpre);
    cudaGetSymbolAddress((void**)&k,    g_k);
    cudaGetSymbolAddress((void**)&v,    g_v);
    cudaGetSymbolAddress((void**)&kv,   g_kv);
    cudaGetSymbolAddress((void**)&o,    g_o);
    (void)q; (void)k; (void)kv; (void)o;   // used via device symbols in kernels

    const int M = Bb * Ls;   // 4096

    // QKV projections
    sgemm_nn<<<dim3(HD / 128, M / 128), 256>>>(x, Wq, qpre, M, HD, HIDd);
    sgemm_nn<<<dim3(KD / 128, M / 128), 256>>>(x, Wk, kpre, M, KD, HIDd);
    sgemm_nn<<<dim3(KD / 128, M / 128), 256>>>(x, Wv, v,    M, KD, HIDd);

    // depthwise conv + silu
    conv_silu<<<(M * HD + 255) / 256, 256>>>(qpre, cqw, cqb, q, HD, M * HD);
    conv_silu<<<(M * KD + 255) / 256, 256>>>(kpre, ckw, ckb, k, KD, M * KD);

    // lightning attention
    kvloc_kernel<<<dim3(4, 4, Bb * Hh * NB), 256>>>(slope);
    kvprefix<<<(Bb * Hh * Dd * Dd) / 256, 256>>>(slope);
    sc_kernel<<<dim3(4, 4, Bb * Hh * NB), 256>>>(slope);     // writes into g_qpre (now dead)
    out_kernel<<<dim3(4, 4, Bb * Hh * NB), 256>>>(slope);

    // norm + output projection
    rmsnorm_kernel<<<M, 256>>>();
    sgemm_nn<<<dim3(HIDd / 128, M / 128), 256>>>(o, Wo, out, M, HIDd, HD);
}

// round 3
// speedup vs baseline: 2.3731x; 2.3731x over previous
#include <cuda_runtime.h>
#include <cuda_bf16.h>
#include <cstdint>

#define Bb   2
#define Ls   2048
#define Hh   16
#define Dd   256
#define HD   4096   // H*D
#define KD   2048   // HKV*D
#define HIDd 2048
#define NB   8
#define BLK  256

// ---------------- scratch (static device memory; no allocs) ----------------
static __device__ __align__(128) float g_qpre[Bb * Ls * HD];   // q pre-conv; reused as sc later
static __device__ __align__(128) float g_q   [Bb * Ls * HD];
static __device__ __align__(128) float g_kpre[Bb * Ls * KD];
static __device__ __align__(128) float g_k   [Bb * Ls * KD];
static __device__ __align__(128) float g_v   [Bb * Ls * KD];
static __device__ __align__(128) float g_kv  [Bb * Hh * NB * Dd * Dd];
static __device__ __align__(128) float g_o   [Bb * Ls * HD];

// bf16 split operands
static __device__ __align__(128) __nv_bfloat16 g_xh [Bb * Ls * HIDd];
static __device__ __align__(128) __nv_bfloat16 g_xl [Bb * Ls * HIDd];
static __device__ __align__(128) __nv_bfloat16 g_wth[HD * HIDd];       // max transposed weight
static __device__ __align__(128) __nv_bfloat16 g_wtl[HD * HIDd];
static __device__ __align__(128) __nv_bfloat16 g_oh [Bb * Ls * HD];
static __device__ __align__(128) __nv_bfloat16 g_ol [Bb * Ls * HD];

// =======================================================================
// helpers
// =======================================================================
__device__ __forceinline__ uint32_t smem_u32(const void* p) {
    uint32_t a;
    asm("{ .reg .u64 t; cvta.to.shared.u64 t, %1; cvt.u32.u64 %0, t; }" : "=r"(a) : "l"(p));
    return a;
}
__device__ __forceinline__ void split2(float x0, float x1, uint32_t& hi, uint32_t& lo) {
    __nv_bfloat16 h0 = __float2bfloat16_rn(x0);
    __nv_bfloat16 h1 = __float2bfloat16_rn(x1);
    float r0 = x0 - __bfloat162float(h0);
    float r1 = x1 - __bfloat162float(h1);
    __nv_bfloat162 hp; hp.x = h0; hp.y = h1;
    __nv_bfloat162 lp = __floats2bfloat162_rn(r0, r1);
    hi = *reinterpret_cast<uint32_t*>(&hp);
    lo = *reinterpret_cast<uint32_t*>(&lp);
}
#define CPA16(dst, src) asm volatile("cp.async.cg.shared.global [%0], [%1], 16;" :: "r"(dst), "l"(src))
#define CPCOMMIT()      asm volatile("cp.async.commit_group;" ::: "memory")
#define CPWAIT1()       asm volatile("cp.async.wait_group 1;" ::: "memory")
__device__ __forceinline__ uint32_t lds32(uint32_t a) {
    uint32_t v;
    asm volatile("ld.shared.b32 %0, [%1];" : "=r"(v) : "r"(a));
    return v;
}
__device__ __forceinline__ void mma16816(float* d, const uint32_t* a, const uint32_t* b) {
    asm volatile("mma.sync.aligned.m16n8k16.row.col.f32.bf16.bf16.f32 "
                 "{%0,%1,%2,%3}, {%4,%5,%6,%7}, {%8,%9}, {%0,%1,%2,%3};"
                 : "+f"(d[0]), "+f"(d[1]), "+f"(d[2]), "+f"(d[3])
                 : "r"(a[0]), "r"(a[1]), "r"(a[2]), "r"(a[3]), "r"(b[0]), "r"(b[1]));
}

// =======================================================================
// convert kernels
// =======================================================================
__global__ __launch_bounds__(256) void convsplit(const float* __restrict__ in,
                                                 __nv_bfloat16* __restrict__ hi,
                                                 __nv_bfloat16* __restrict__ lo, int n4)
{
    int i = blockIdx.x * 256 + threadIdx.x;
    if (i >= n4) return;
    float4 v = ((const float4*)in)[i];
    uint2 h, l;
    split2(v.x, v.y, h.x, l.x);
    split2(v.z, v.w, h.y, l.y);
    ((uint2*)hi)[i] = h;
    ((uint2*)lo)[i] = l;
}

// W[K][N] fp32 -> Wt[N][K] bf16 hi/lo (tiled transpose)
__global__ __launch_bounds__(256) void tsplit(const float* __restrict__ W,
                                              __nv_bfloat16* __restrict__ th,
                                              __nv_bfloat16* __restrict__ tl,
                                              int Kd, int Nd)
{
    __shared__ float t[32][33];
    const int bxn = blockIdx.x * 32;   // n tile
    const int byk = blockIdx.y * 32;   // k tile
    const int x = threadIdx.x & 31, y = threadIdx.x >> 5;   // 32 x 8
#pragma unroll
    for (int j = 0; j < 4; j++)
        t[y + 8 * j][x] = W[(size_t)(byk + y + 8 * j) * Nd + bxn + x];
    __syncthreads();
    const int n = bxn + x;
#pragma unroll
    for (int jj = 0; jj < 1; jj++) {
        float v0 = t[y * 4 + 0][x];
        float v1 = t[y * 4 + 1][x];
        float v2 = t[y * 4 + 2][x];
        float v3 = t[y * 4 + 3][x];
        uint2 h, l;
        split2(v0, v1, h.x, l.x);
        split2(v2, v3, h.y, l.y);
        size_t off = ((size_t)n * Kd + byk + y * 4) >> 2;   // in uint2 units (4 bf16)
        ((uint2*)th)[off] = h;
        ((uint2*)tl)[off] = l;
    }
}

// =======================================================================
// HMMA GEMM: C[M,N] fp32 = A[M,K] @ Bt[N,K]^T via 3-term bf16 split
// tile 128x128, BK=64, double-buffered cp.async, SW128-style swizzle
// =======================================================================
#define SA_H 0
#define SA_L 16384
#define SB_H 32768
#define SB_L 49152
#define STAGE_B 65536
#define HG_SMEM (2 * STAGE_B)

__global__ __launch_bounds__(256, 1) void hgemm(const __nv_bfloat16* __restrict__ Ah,
                                                const __nv_bfloat16* __restrict__ Al,
                                                const __nv_bfloat16* __restrict__ Bh,
                                                const __nv_bfloat16* __restrict__ Bl,
                                                float* __restrict__ C,
                                                int M, int N, int K)
{
    extern __shared__ char sm[];
    const uint32_t sbase = smem_u32(sm);
    const int tid = threadIdx.x, wid = tid >> 5, lane = tid & 31;
    const int m0 = blockIdx.y * 128, n0 = blockIdx.x * 128;
    const int wm = (wid & 1) * 64, wn = (wid >> 1) * 32;
    const int t4 = lane & 3, tq = lane >> 2;

    float acc[4][4][4];
#pragma unroll
    for (int a = 0; a < 4; a++)
#pragma unroll
        for (int b = 0; b < 4; b++)
#pragma unroll
            for (int c = 0; c < 4; c++) acc[a][b][c] = 0.f;

    const int fr = tid >> 3;     // 0..31
    const int fc = tid & 7;      // 0..7

#define FILL(s, buf) do {                                                                 \
    const uint32_t sb = sbase + (buf) * STAGE_B;                                          \
    const int k0 = (s) * 64;                                                              \
    _Pragma("unroll")                                                                     \
    for (int i = 0; i < 4; i++) {                                                         \
        int r = fr + 32 * i;                                                              \
        uint32_t doff = (uint32_t)(r * 128 + ((fc ^ (r & 7)) << 4));                      \
        const size_t so = (size_t)(m0 + r) * K + k0 + fc * 8;                             \
        CPA16(sb + SA_H + doff, Ah + so);                                                 \
        CPA16(sb + SA_L + doff, Al + so);                                                 \
        const size_t sob = (size_t)(n0 + r) * K + k0 + fc * 8;                            \
        CPA16(sb + SB_H + doff, Bh + sob);                                                \
        CPA16(sb + SB_L + doff, Bl + sob);                                                \
    }                                                                                     \
} while (0)

    const int S = K / 64;
    FILL(0, 0); CPCOMMIT();
    FILL(1, 1); CPCOMMIT();

    for (int s = 0; s < S; s++) {
        CPWAIT1();
        __syncthreads();
        const uint32_t sb = sbase + (s & 1) * STAGE_B;

#pragma unroll
        for (int kk = 0; kk < 4; kk++) {
            uint32_t ah[4][4], al[4][4], bh[4][2], bl[4][2];
#pragma unroll
            for (int mi = 0; mi < 4; mi++) {
                const int m = wm + mi * 16 + tq;
                const uint32_t e = (uint32_t)(m & 7);
                const uint32_t rp = sb + (uint32_t)(m * 128) + t4 * 4;
                const uint32_t o0 = (uint32_t)((2 * kk) ^ e) << 4;
                const uint32_t o1 = (uint32_t)((2 * kk + 1) ^ e) << 4;
                ah[mi][0] = lds32(rp + SA_H + o0);
                ah[mi][1] = lds32(rp + SA_H + o0 + 1024);
                ah[mi][2] = lds32(rp + SA_H + o1);
                ah[mi][3] = lds32(rp + SA_H + o1 + 1024);
                al[mi][0] = lds32(rp + SA_L + o0);
                al[mi][1] = lds32(rp + SA_L + o0 + 1024);
                al[mi][2] = lds32(rp + SA_L + o1);
                al[mi][3] = lds32(rp + SA_L + o1 + 1024);
            }
#pragma unroll
            for (int ni = 0; ni < 4; ni++) {
                const int n = wn + ni * 8 + tq;
                const uint32_t e = (uint32_t)(n & 7);
                const uint32_t rp = sb + (uint32_t)(n * 128) + t4 * 4;
                const uint32_t o0 = (uint32_t)((2 * kk) ^ e) << 4;
                const uint32_t o1 = (uint32_t)((2 * kk + 1) ^ e) << 4;
                bh[ni][0] = lds32(rp + SB_H + o0);
                bh[ni][1] = lds32(rp + SB_H + o1);
                bl[ni][0] = lds32(rp + SB_L + o0);
                bl[ni][1] = lds32(rp + SB_L + o1);
            }
#pragma unroll
            for (int mi = 0; mi < 4; mi++)
#pragma unroll
                for (int ni = 0; ni < 4; ni++) {
                    mma16816(acc[mi][ni], ah[mi], bh[ni]);
                    mma16816(acc[mi][ni], al[mi], bh[ni]);
                    mma16816(acc[mi][ni], ah[mi], bl[ni]);
                }
        }
        __syncthreads();
        if (s + 2 < S) FILL(s + 2, s & 1);
        CPCOMMIT();
    }

    // epilogue
#pragma unroll
    for (int mi = 0; mi < 4; mi++) {
        const int m = m0 + wm + mi * 16 + tq;
#pragma unroll
        for (int ni = 0; ni < 4; ni++) {
            const int n = n0 + wn + ni * 8 + t4 * 2;
            float* cp0 = C + (size_t)m * N + n;
            float* cp1 = C + (size_t)(m + 8) * N + n;
            *(float2*)cp0 = make_float2(acc[mi][ni][0], acc[mi][ni][1]);
            *(float2*)cp1 = make_float2(acc[mi][ni][2], acc[mi][ni][3]);
        }
    }
#undef FILL
}

// ---------------- depthwise causal conv (K=4) + SiLU ----------------
__global__ __launch_bounds__(256) void conv_silu(const float* __restrict__ in,
                                                 const float* __restrict__ w,
                                                 const float* __restrict__ bias,
                                                 float* __restrict__ out,
                                                 int C, int total)
{
    int i = blockIdx.x * blockDim.x + threadIdx.x;
    if (i >= total) return;
    int c = i % C;
    int l = (i / C) % Ls;
    float acc = bias[c];
#pragma unroll
    for (int t = 0; t < 4; t++) {
        int ls = l + t - 3;
        if (ls >= 0) acc += w[c * 4 + t] * in[i + (t - 3) * C];
    }
    out[i] = acc / (1.f + expf(-acc));
}

// ---------------- local KV per (b,h,chunk) ----------------
__global__ __launch_bounds__(256) void kvloc_kernel(const float* __restrict__ slope)
{
    const int z = blockIdx.z;
    const int b = z / (Hh * NB);
    const int h = (z / NB) % Hh;
    const int c = z % NB;
    const int kvh = h >> 1;
    const float s = slope[h];

    const float* kb = g_k + (size_t)(b * Ls + c * BLK) * KD + kvh * Dd;
    const float* vb = g_v + (size_t)(b * Ls + c * BLK) * KD + kvh * Dd;
    const int d0 = blockIdx.y * 64, e0 = blockIdx.x * 64;

    __shared__ float As[16][64];
    __shared__ float Bs[16][64];
    const int tid = threadIdx.x;
    const int ty = tid >> 4, tx = tid & 15;
    const int nl = tid >> 4;
    const int cq = (tid & 15) * 4;

    float acc[4][4] = {};
    for (int n0 = 0; n0 < BLK; n0 += 16) {
        const int n = n0 + nl;
        const float kd = expf(-s * (float)(BLK - 1 - n));
        float4 a  = *(const float4*)(kb + (size_t)n * KD + d0 + cq);
        float4 bb = *(const float4*)(vb + (size_t)n * KD + e0 + cq);
        As[nl][cq + 0] = kd * a.x;
        As[nl][cq + 1] = kd * a.y;
        As[nl][cq + 2] = kd * a.z;
        As[nl][cq + 3] = kd * a.w;
        *(float4*)&Bs[nl][cq] = bb;
        __syncthreads();
#pragma unroll
        for (int kk = 0; kk < 16; kk++) {
            float4 a4 = *(const float4*)&As[kk][ty * 4];
            float4 b4 = *(const float4*)&Bs[kk][tx * 4];
            float av[4] = {a4.x, a4.y, a4.z, a4.w};
            float bv[4] = {b4.x, b4.y, b4.z, b4.w};
#pragma unroll
            for (int i = 0; i < 4; i++)
#pragma unroll
                for (int j = 0; j < 4; j++) acc[i][j] += av[i] * bv[j];
        }
        __syncthreads();
    }
    float* outp = g_kv + (size_t)z * Dd * Dd;
#pragma unroll
    for (int i = 0; i < 4; i++) {
        float* op = outp + (size_t)(d0 + ty * 4 + i) * Dd + e0 + tx * 4;
        *(float4*)op = make_float4(acc[i][0], acc[i][1], acc[i][2], acc[i][3]);
    }
}

// ---------------- in-place exclusive decay prefix over chunks ----------------
__global__ __launch_bounds__(256) void kvprefix(const float* __restrict__ slope)
{
    const int idx = blockIdx.x * blockDim.x + threadIdx.x;
    const int bh = idx >> 16;
    const int de = idx & 65535;
    const int h = bh % Hh;
    const float bdec = expf(-slope[h] * (float)BLK);
    float acc = 0.f;
    float* p = g_kv + (size_t)bh * NB * 65536 + de;
#pragma unroll
    for (int c = 0; c < NB; c++) {
        float loc = p[(size_t)c * 65536];
        p[(size_t)c * 65536] = acc;
        acc = acc * bdec + loc;
    }
}

// ---------------- masked decayed scores ----------------
__global__ __launch_bounds__(256) void sc_kernel(const float* __restrict__ slope)
{
    const int z = blockIdx.z;
    const int b = z / (Hh * NB);
    const int h = (z / NB) % Hh;
    const int c = z % NB;
    const int kvh = h >> 1;
    const float s = slope[h];

    const float* qb = g_q + (size_t)(b * Ls + c * BLK) * HD + h * Dd;
    const float* kb = g_k + (size_t)(b * Ls + c * BLK) * KD + kvh * Dd;
    const int m0 = blockIdx.y * 64, n0 = blockIdx.x * 64;

    __shared__ float As[16][64];
    __shared__ float Bs[16][64];
    const int tid = threadIdx.x;
    const int ty = tid >> 4, tx = tid & 15;
    const int rl = tid >> 2;
    const int dq = (tid & 3) * 4;

    float acc[4][4] = {};
    for (int dd = 0; dd < Dd; dd += 16) {
        float4 a  = *(const float4*)(qb + (size_t)(m0 + rl) * HD + dd + dq);
        float4 bb = *(const float4*)(kb + (size_t)(n0 + rl) * KD + dd + dq);
        As[dq + 0][rl] = a.x;  As[dq + 1][rl] = a.y;
        As[dq + 2][rl] = a.z;  As[dq + 3][rl] = a.w;
        Bs[dq + 0][rl] = bb.x; Bs[dq + 1][rl] = bb.y;
        Bs[dq + 2][rl] = bb.z; Bs[dq + 3][rl] = bb.w;
        __syncthreads();
#pragma unroll
        for (int kk = 0; kk < 16; kk++) {
            float4 a4 = *(const float4*)&As[kk][ty * 4];
            float4 b4 = *(const float4*)&Bs[kk][tx * 4];
            float av[4] = {a4.x, a4.y, a4.z, a4.w};
            float bv[4] = {b4.x, b4.y, b4.z, b4.w};
#pragma unroll
            for (int i = 0; i < 4; i++)
#pragma unroll
                for (int j = 0; j < 4; j++) acc[i][j] += av[i] * bv[j];
        }
        __syncthreads();
    }
    float* scp = g_qpre + (size_t)z * 65536;
#pragma unroll
    for (int i = 0; i < 4; i++)
#pragma unroll
        for (int j = 0; j < 4; j++) {
            int m = m0 + ty * 4 + i, n = n0 + tx * 4 + j;
            float v = (m >= n) ? acc[i][j] * expf(-s * (float)(m - n)) : 0.f;
            scp[(size_t)m * BLK + n] = v;
        }
}

// ---------------- output: o = (q*qdec) @ kv_in + sc @ v ----------------
__global__ __launch_bounds__(256) void out_kernel(const float* __restrict__ slope)
{
    const int z = blockIdx.z;
    const int b = z / (Hh * NB);
    const int h = (z / NB) % Hh;
    const int c = z % NB;
    const int kvh = h >> 1;
    const float s = slope[h];

    const float* qb  = g_q    + (size_t)(b * Ls + c * BLK) * HD + h * Dd;
    const float* vb  = g_v    + (size_t)(b * Ls + c * BLK) * KD + kvh * Dd;
    const float* kvp = g_kv   + (size_t)z * 65536;
    const float* scp = g_qpre + (size_t)z * 65536;
    const int m0 = blockIdx.y * 64, e0 = blockIdx.x * 64;

    __shared__ float As[16][64];
    __shared__ float Bs[16][64];
    const int tid = threadIdx.x;
    const int ty = tid >> 4, tx = tid & 15;
    const int rl  = tid >> 2;
    const int dq  = (tid & 3) * 4;
    const int rl2 = tid >> 4;
    const int eq  = (tid & 15) * 4;

    float acc[4][4] = {};

    for (int dd = 0; dd < Dd; dd += 16) {
        const int m = m0 + rl;
        const float qdec = expf(-s * (float)(m + 1));
        float4 a = *(const float4*)(qb + (size_t)m * HD + dd + dq);
        As[dq + 0][rl] = qdec * a.x;
        As[dq + 1][rl] = qdec * a.y;
        As[dq + 2][rl] = qdec * a.z;
        As[dq + 3][rl] = qdec * a.w;
        float4 bb = *(const float4*)(kvp + (size_t)(dd + rl2) * Dd + e0 + eq);
        *(float4*)&Bs[rl2][eq] = bb;
        __syncthreads();
#pragma unroll
        for (int kk = 0; kk < 16; kk++) {
            float4 a4 = *(const float4*)&As[kk][ty * 4];
            float4 b4 = *(const float4*)&Bs[kk][tx * 4];
            float av[4] = {a4.x, a4.y, a4.z, a4.w};
            float bv[4] = {b4.x, b4.y, b4.z, b4.w};
#pragma unroll
            for (int i = 0; i < 4; i++)
#pragma unroll
                for (int j = 0; j < 4; j++) acc[i][j] += av[i] * bv[j];
        }
        __syncthreads();
    }

    for (int nn = 0; nn < BLK; nn += 16) {
        float4 a = *(const float4*)(scp + (size_t)(m0 + rl) * BLK + nn + dq);
        As[dq + 0][rl] = a.x;  As[dq + 1][rl] = a.y;
        As[dq + 2][rl] = a.z;  As[dq + 3][rl] = a.w;
        float4 bb = *(const float4*)(vb + (size_t)(nn + rl2) * KD + e0 + eq);
        *(float4*)&Bs[rl2][eq] = bb;
        __syncthreads();
#pragma unroll
        for (int kk = 0; kk < 16; kk++) {
            float4 a4 = *(const float4*)&As[kk][ty * 4];
            float4 b4 = *(const float4*)&Bs[kk][tx * 4];
            float av[4] = {a4.x, a4.y, a4.z, a4.w};
            float bv[4] = {b4.x, b4.y, b4.z, b4.w};
#pragma unroll
            for (int i = 0; i < 4; i++)
#pragma unroll
                for (int j = 0; j < 4; j++) acc[i][j] += av[i] * bv[j];
        }
        __syncthreads();
    }

#pragma unroll
    for (int i = 0; i < 4; i++) {
        const int m = m0 + ty * 4 + i;
        float* op = g_o + (size_t)(b * Ls + c * BLK + m) * HD + h * Dd + e0 + tx * 4;
        *(float4*)op = make_float4(acc[i][0], acc[i][1], acc[i][2], acc[i][3]);
    }
}

// ---------------- SimpleRMSNorm + bf16 hi/lo split output ----------------
__global__ __launch_bounds__(256) void rmsnorm_split_kernel()
{
    const int row = blockIdx.x;
    const float* p = g_o + (size_t)row * HD;
    __nv_bfloat16* oh = g_oh + (size_t)row * HD;
    __nv_bfloat16* ol = g_ol + (size_t)row * HD;
    const int tid = threadIdx.x;
    float ss = 0.f;
    for (int i = tid; i < HD; i += 256) {
        float v = p[i];
        ss += v * v;
    }
#pragma unroll
    for (int off = 16; off > 0; off >>= 1) ss += __shfl_xor_sync(0xffffffffu, ss, off);
    __shared__ float red[8];
    __shared__ float scale_s;
    if ((tid & 31) == 0) red[tid >> 5] = ss;
    __syncthreads();
    if (tid == 0) {
        float tot = 0.f;
#pragma unroll
        for (int w = 0; w < 8; w++) tot += red[w];
        scale_s = rsqrtf(tot / (float)HD + 1e-6f);
    }
    __syncthreads();
    const float sc = scale_s;
    for (int i = tid * 2; i < HD; i += 512) {
        float v0 = p[i] * sc, v1 = p[i + 1] * sc;
        uint32_t h, l;
        split2(v0, v1, h, l);
        *(uint32_t*)(oh + i) = h;
        *(uint32_t*)(ol + i) = l;
    }
}

// ---------------- launcher ----------------
extern "C" void kernel_launch(void* const* d_in, const int* in_sizes, int n_in,
                              void* d_out, int out_size)
{
    const float* x     = (const float*)d_in[0];
    const float* Wq    = (const float*)d_in[1];
    const float* Wk    = (const float*)d_in[2];
    const float* Wv    = (const float*)d_in[3];
    const float* Wo    = (const float*)d_in[4];
    const float* cqw   = (const float*)d_in[5];
    const float* cqb   = (const float*)d_in[6];
    const float* ckw   = (const float*)d_in[7];
    const float* ckb   = (const float*)d_in[8];
    const float* slope = (const float*)d_in[9];
    float* out = (float*)d_out;

    float *qpre, *q, *kpre, *k, *v, *o;
    __nv_bfloat16 *xh, *xl, *wth, *wtl, *oh, *ol;
    cudaGetSymbolAddress((void**)&qpre, g_qpre);
    cudaGetSymbolAddress((void**)&q,    g_q);
    cudaGetSymbolAddress((void**)&kpre, g_kpre);
    cudaGetSymbolAddress((void**)&k,    g_k);
    cudaGetSymbolAddress((void**)&v,    g_v);
    cudaGetSymbolAddress((void**)&o,    g_o);
    cudaGetSymbolAddress((void**)&xh,   g_xh);
    cudaGetSymbolAddress((void**)&xl,   g_xl);
    cudaGetSymbolAddress((void**)&wth,  g_wth);
    cudaGetSymbolAddress((void**)&wtl,  g_wtl);
    cudaGetSymbolAddress((void**)&oh,   g_oh);
    cudaGetSymbolAddress((void**)&ol,   g_ol);
    (void)q; (void)k;

    cudaFuncSetAttribute(hgemm, cudaFuncAttributeMaxDynamicSharedMemorySize, HG_SMEM);

    const int M = Bb * Ls;   // 4096

    // split x once
    convsplit<<<(M * HIDd / 4 + 255) / 256, 256>>>(x, xh, xl, M * HIDd / 4);

    // Q projection
    tsplit<<<dim3(HD / 32, HIDd / 32), 256>>>(Wq, wth, wtl, HIDd, HD);
    hgemm<<<dim3(HD / 128, M / 128), 256, HG_SMEM>>>(xh, xl, wth, wtl, qpre, M, HD, HIDd);
    // K projection
    tsplit<<<dim3(KD / 32, HIDd / 32), 256>>>(Wk, wth, wtl, HIDd, KD);
    hgemm<<<dim3(KD / 128, M / 128), 256, HG_SMEM>>>(xh, xl, wth, wtl, kpre, M, KD, HIDd);
    // V projection
    tsplit<<<dim3(KD / 32, HIDd / 32), 256>>>(Wv, wth, wtl, HIDd, KD);
    hgemm<<<dim3(KD / 128, M / 128), 256, HG_SMEM>>>(xh, xl, wth, wtl, v, M, KD, HIDd);

    // depthwise conv + silu
    conv_silu<<<(M * HD + 255) / 256, 256>>>(qpre, cqw, cqb, q, HD, M * HD);
    conv_silu<<<(M * KD + 255) / 256, 256>>>(kpre, ckw, ckb, k, KD, M * KD);

    // lightning attention
    kvloc_kernel<<<dim3(4, 4, Bb * Hh * NB), 256>>>(slope);
    kvprefix<<<(Bb * Hh * Dd * Dd) / 256, 256>>>(slope);
    sc_kernel<<<dim3(4, 4, Bb * Hh * NB), 256>>>(slope);
    out_kernel<<<dim3(4, 4, Bb * Hh * NB), 256>>>(slope);

    // norm + split + output projection
    rmsnorm_split_kernel<<<M, 256>>>();
    tsplit<<<dim3(HIDd / 32, HD / 32), 256>>>(Wo, wth, wtl, HD, HIDd);
    hgemm<<<dim3(HIDd / 128, M / 128), 256, HG_SMEM>>>(oh, ol, wth, wtl, out, M, HIDd, HD);
}

// round 4
// speedup vs baseline: 3.1032x; 1.3076x over previous
#include <cuda_runtime.h>
#include <cuda_bf16.h>
#include <cstdint>

#define Bb   2
#define Ls   2048
#define Hh   16
#define Dd   256
#define HD   4096   // H*D
#define KD   2048   // HKV*D
#define HIDd 2048
#define NB   8
#define BLK  256

// ---------------- scratch (static device memory; no allocs) ----------------
static __device__ __align__(128) float g_qpre[Bb * Ls * HD];
static __device__ __align__(128) float g_kpre[Bb * Ls * KD];
static __device__ __align__(128) float g_k   [Bb * Ls * KD];     // k fp32 (for transpose)
static __device__ __align__(128) float g_v   [Bb * Ls * KD];     // v fp32 (for transpose)
static __device__ __align__(128) float g_kv  [Bb * Hh * NB * Dd * Dd];  // kvT fp32
static __device__ __align__(128) float g_o   [Bb * Ls * HD];
static __device__ __align__(128) float g_kT  [16 * Dd * Ls];     // kT fp32 [b*8+hk][d][l]

// bf16 split operands
static __device__ __align__(128) __nv_bfloat16 g_xh [Bb * Ls * HIDd];
static __device__ __align__(128) __nv_bfloat16 g_xl [Bb * Ls * HIDd];
static __device__ __align__(128) __nv_bfloat16 g_wth[HD * HIDd];
static __device__ __align__(128) __nv_bfloat16 g_wtl[HD * HIDd];
static __device__ __align__(128) __nv_bfloat16 g_oh [Bb * Ls * HD];
static __device__ __align__(128) __nv_bfloat16 g_ol [Bb * Ls * HD];
static __device__ __align__(128) __nv_bfloat16 g_qh [Bb * Ls * HD];
static __device__ __align__(128) __nv_bfloat16 g_ql [Bb * Ls * HD];
static __device__ __align__(128) __nv_bfloat16 g_kh [Bb * Ls * KD];
static __device__ __align__(128) __nv_bfloat16 g_kl [Bb * Ls * KD];
static __device__ __align__(128) __nv_bfloat16 g_vTh[16 * Dd * Ls];
static __device__ __align__(128) __nv_bfloat16 g_vTl[16 * Dd * Ls];
static __device__ __align__(128) __nv_bfloat16 g_kvTh[Bb * Hh * NB * Dd * Dd];
static __device__ __align__(128) __nv_bfloat16 g_kvTl[Bb * Hh * NB * Dd * Dd];
static __device__ __align__(128) __nv_bfloat16 g_sch[Bb * Hh * NB * BLK * BLK];
static __device__ __align__(128) __nv_bfloat16 g_scl[Bb * Hh * NB * BLK * BLK];

// =======================================================================
// helpers
// =======================================================================
__device__ __forceinline__ uint32_t smem_u32(const void* p) {
    uint32_t a;
    asm("{ .reg .u64 t; cvta.to.shared.u64 t, %1; cvt.u32.u64 %0, t; }" : "=r"(a) : "l"(p));
    return a;
}
__device__ __forceinline__ void split2(float x0, float x1, uint32_t& hi, uint32_t& lo) {
    __nv_bfloat16 h0 = __float2bfloat16_rn(x0);
    __nv_bfloat16 h1 = __float2bfloat16_rn(x1);
    float r0 = x0 - __bfloat162float(h0);
    float r1 = x1 - __bfloat162float(h1);
    __nv_bfloat162 hp; hp.x = h0; hp.y = h1;
    __nv_bfloat162 lp = __floats2bfloat162_rn(r0, r1);
    hi = *reinterpret_cast<uint32_t*>(&hp);
    lo = *reinterpret_cast<uint32_t*>(&lp);
}
#define CPA16(dst, src) asm volatile("cp.async.cg.shared.global [%0], [%1], 16;" :: "r"(dst), "l"(src))
#define CPCOMMIT()      asm volatile("cp.async.commit_group;" ::: "memory")
#define CPWAIT1()       asm volatile("cp.async.wait_group 1;" ::: "memory")
__device__ __forceinline__ uint32_t lds32(uint32_t a) {
    uint32_t v;
    asm volatile("ld.shared.b32 %0, [%1];" : "=r"(v) : "r"(a));
    return v;
}
__device__ __forceinline__ void mma16816(float* d, const uint32_t* a, const uint32_t* b) {
    asm volatile("mma.sync.aligned.m16n8k16.row.col.f32.bf16.bf16.f32 "
                 "{%0,%1,%2,%3}, {%4,%5,%6,%7}, {%8,%9}, {%0,%1,%2,%3};"
                 : "+f"(d[0]), "+f"(d[1]), "+f"(d[2]), "+f"(d[3])
                 : "r"(a[0]), "r"(a[1]), "r"(a[2]), "r"(a[3]), "r"(b[0]), "r"(b[1]));
}

// shared-tile SMEM layout (all MMA kernels)
#define SA_H 0
#define SA_L 16384
#define SB_H 32768
#define SB_L 49152
#define STAGE_B 65536
#define HG_SMEM (2 * STAGE_B)

// one BK=64 stage of the 3-term split MMA (identical to validated hgemm inner)
__device__ __forceinline__ void stage_mma(uint32_t sb, float acc[4][4][4],
                                          int wm, int wn, int tq, int t4)
{
#pragma unroll
    for (int kk = 0; kk < 4; kk++) {
        uint32_t ah[4][4], al[4][4], bh[4][2], bl[4][2];
#pragma unroll
        for (int mi = 0; mi < 4; mi++) {
            const int m = wm + mi * 16 + tq;
            const uint32_t e = (uint32_t)(m & 7);
            const uint32_t rp = sb + (uint32_t)(m * 128) + t4 * 4;
            const uint32_t o0 = (uint32_t)((2 * kk) ^ e) << 4;
            const uint32_t o1 = (uint32_t)((2 * kk + 1) ^ e) << 4;
            ah[mi][0] = lds32(rp + SA_H + o0);
            ah[mi][1] = lds32(rp + SA_H + o0 + 1024);
            ah[mi][2] = lds32(rp + SA_H + o1);
            ah[mi][3] = lds32(rp + SA_H + o1 + 1024);
            al[mi][0] = lds32(rp + SA_L + o0);
            al[mi][1] = lds32(rp + SA_L + o0 + 1024);
            al[mi][2] = lds32(rp + SA_L + o1);
            al[mi][3] = lds32(rp + SA_L + o1 + 1024);
        }
#pragma unroll
        for (int ni = 0; ni < 4; ni++) {
            const int n = wn + ni * 8 + tq;
            const uint32_t e = (uint32_t)(n & 7);
            const uint32_t rp = sb + (uint32_t)(n * 128) + t4 * 4;
            const uint32_t o0 = (uint32_t)((2 * kk) ^ e) << 4;
            const uint32_t o1 = (uint32_t)((2 * kk + 1) ^ e) << 4;
            bh[ni][0] = lds32(rp + SB_H + o0);
            bh[ni][1] = lds32(rp + SB_H + o1);
            bl[ni][0] = lds32(rp + SB_L + o0);
            bl[ni][1] = lds32(rp + SB_L + o1);
        }
#pragma unroll
        for (int mi = 0; mi < 4; mi++)
#pragma unroll
            for (int ni = 0; ni < 4; ni++) {
                mma16816(acc[mi][ni], ah[mi], bh[ni]);
                mma16816(acc[mi][ni], al[mi], bh[ni]);
                mma16816(acc[mi][ni], ah[mi], bl[ni]);
            }
    }
}

// cp.async fill of one hi/lo operand tile (128 rows x 64 cols bf16), gh/gl point at tile row0+k0
__device__ __forceinline__ void fill_pair(uint32_t sb_h, uint32_t sb_l,
                                          const __nv_bfloat16* gh, const __nv_bfloat16* gl,
                                          size_t stride, int fr, int fc)
{
#pragma unroll
    for (int i = 0; i < 4; i++) {
        int r = fr + 32 * i;
        uint32_t doff = (uint32_t)(r * 128 + ((fc ^ (r & 7)) << 4));
        size_t so = (size_t)r * stride + fc * 8;
        CPA16(sb_h + doff, gh + so);
        CPA16(sb_l + doff, gl + so);
    }
}

// manual fill from fp32 with per-column decay scaling, split hi/lo
__device__ __forceinline__ void fill_f32_decay(char* smh, char* sml,
                                               const float* g, size_t stride,
                                               int fr, int fc, float kd0, float ek)
{
    float kd[8];
    kd[0] = kd0;
#pragma unroll
    for (int j = 1; j < 8; j++) kd[j] = kd[j - 1] * ek;
#pragma unroll
    for (int i = 0; i < 4; i++) {
        int r = fr + 32 * i;
        uint32_t doff = (uint32_t)(r * 128 + ((fc ^ (r & 7)) << 4));
        const float* sp = g + (size_t)r * stride + fc * 8;
        float4 u = *(const float4*)sp;
        float4 w = *(const float4*)(sp + 4);
        uint4 hi, lo;
        split2(u.x * kd[0], u.y * kd[1], hi.x, lo.x);
        split2(u.z * kd[2], u.w * kd[3], hi.y, lo.y);
        split2(w.x * kd[4], w.y * kd[5], hi.z, lo.z);
        split2(w.z * kd[6], w.w * kd[7], hi.w, lo.w);
        *(uint4*)(smh + doff) = hi;
        *(uint4*)(sml + doff) = lo;
    }
}

// =======================================================================
// convert kernels
// =======================================================================
__global__ __launch_bounds__(256) void convsplit(const float* __restrict__ in,
                                                 __nv_bfloat16* __restrict__ hi,
                                                 __nv_bfloat16* __restrict__ lo, int n4)
{
    int i = blockIdx.x * 256 + threadIdx.x;
    if (i >= n4) return;
    float4 v = ((const float4*)in)[i];
    uint2 h, l;
    split2(v.x, v.y, h.x, l.x);
    split2(v.z, v.w, h.y, l.y);
    ((uint2*)hi)[i] = h;
    ((uint2*)lo)[i] = l;
}

__global__ __launch_bounds__(256) void tsplit(const float* __restrict__ W,
                                              __nv_bfloat16* __restrict__ th,
                                              __nv_bfloat16* __restrict__ tl,
                                              int Kd, int Nd)
{
    __shared__ float t[32][33];
    const int bxn = blockIdx.x * 32;
    const int byk = blockIdx.y * 32;
    const int x = threadIdx.x & 31, y = threadIdx.x >> 5;
#pragma unroll
    for (int j = 0; j < 4; j++)
        t[y + 8 * j][x] = W[(size_t)(byk + y + 8 * j) * Nd + bxn + x];
    __syncthreads();
    const int n = bxn + x;
    float v0 = t[y * 4 + 0][x];
    float v1 = t[y * 4 + 1][x];
    float v2 = t[y * 4 + 2][x];
    float v3 = t[y * 4 + 3][x];
    uint2 h, l;
    split2(v0, v1, h.x, l.x);
    split2(v2, v3, h.y, l.y);
    size_t off = ((size_t)n * Kd + byk + y * 4) >> 2;
    ((uint2*)th)[off] = h;
    ((uint2*)tl)[off] = l;
}

// transpose fp32 [b,l,hk,d] -> fp32 [b*8+hk][d][l]
__global__ __launch_bounds__(256) void trans_f32(const float* __restrict__ in,
                                                 float* __restrict__ out)
{
    __shared__ float t[32][33];
    const int bk = blockIdx.z;
    const int b = bk >> 3, hk = bk & 7;
    const int l0 = blockIdx.x * 32, d0 = blockIdx.y * 32;
    const int x = threadIdx.x & 31, y = threadIdx.x >> 5;
#pragma unroll
    for (int j = 0; j < 4; j++)
        t[y + 8 * j][x] = in[(size_t)(b * Ls + l0 + y + 8 * j) * KD + hk * Dd + d0 + x];
    __syncthreads();
#pragma unroll
    for (int j = 0; j < 4; j++) {
        int d = d0 + y + 8 * j;
        out[((size_t)bk * Dd + d) * Ls + l0 + x] = t[x][y + 8 * j];
    }
}

// transpose fp32 [b,l,hk,d] -> bf16 hi/lo [b*8+hk][d][l]
__global__ __launch_bounds__(256) void trans_split(const float* __restrict__ in,
                                                   __nv_bfloat16* __restrict__ oth,
                                                   __nv_bfloat16* __restrict__ otl)
{
    __shared__ float t[32][33];
    const int bk = blockIdx.z;
    const int b = bk >> 3, hk = bk & 7;
    const int l0 = blockIdx.x * 32, d0 = blockIdx.y * 32;
    const int x = threadIdx.x & 31, y = threadIdx.x >> 5;
#pragma unroll
    for (int j = 0; j < 4; j++)
        t[y + 8 * j][x] = in[(size_t)(b * Ls + l0 + y + 8 * j) * KD + hk * Dd + d0 + x];
    __syncthreads();
    const int x2 = threadIdx.x & 15, yy = threadIdx.x >> 4;
#pragma unroll
    for (int j = 0; j < 2; j++) {
        int d = d0 + yy + 16 * j;
        float v0 = t[x2 * 2][yy + 16 * j];
        float v1 = t[x2 * 2 + 1][yy + 16 * j];
        uint32_t h, l;
        split2(v0, v1, h, l);
        size_t off = (((size_t)bk * Dd + d) * Ls + l0 + x2 * 2) >> 1;
        ((uint32_t*)oth)[off] = h;
        ((uint32_t*)otl)[off] = l;
    }
}

// =======================================================================
// HMMA GEMM (big projections) — unchanged from R3
// =======================================================================
__global__ __launch_bounds__(256, 1) void hgemm(const __nv_bfloat16* __restrict__ Ah,
                                                const __nv_bfloat16* __restrict__ Al,
                                                const __nv_bfloat16* __restrict__ Bh,
                                                const __nv_bfloat16* __restrict__ Bl,
                                                float* __restrict__ C,
                                                int M, int N, int K)
{
    extern __shared__ char sm[];
    const uint32_t sbase = smem_u32(sm);
    const int tid = threadIdx.x, wid = tid >> 5, lane = tid & 31;
    const int m0 = blockIdx.y * 128, n0 = blockIdx.x * 128;
    const int wm = (wid & 1) * 64, wn = (wid >> 1) * 32;
    const int t4 = lane & 3, tq = lane >> 2;

    float acc[4][4][4] = {};
    const int fr = tid >> 3;
    const int fc = tid & 7;

#define FILLG(s, buf) do {                                                                \
    const uint32_t sb = sbase + (buf) * STAGE_B;                                          \
    const int k0 = (s) * 64;                                                              \
    fill_pair(sb + SA_H, sb + SA_L, Ah + (size_t)m0 * K + k0, Al + (size_t)m0 * K + k0, K, fr, fc); \
    fill_pair(sb + SB_H, sb + SB_L, Bh + (size_t)n0 * K + k0, Bl + (size_t)n0 * K + k0, K, fr, fc); \
} while (0)

    const int S = K / 64;
    FILLG(0, 0); CPCOMMIT();
    FILLG(1, 1); CPCOMMIT();

    for (int s = 0; s < S; s++) {
        CPWAIT1();
        __syncthreads();
        stage_mma(sbase + (s & 1) * STAGE_B, acc, wm, wn, tq, t4);
        __syncthreads();
        if (s + 2 < S) FILLG(s + 2, s & 1);
        CPCOMMIT();
    }
#undef FILLG

#pragma unroll
    for (int mi = 0; mi < 4; mi++) {
        const int m = m0 + wm + mi * 16 + tq;
#pragma unroll
        for (int ni = 0; ni < 4; ni++) {
            const int n = n0 + wn + ni * 8 + t4 * 2;
            float* cp0 = C + (size_t)m * N + n;
            float* cp1 = C + (size_t)(m + 8) * N + n;
            *(float2*)cp0 = make_float2(acc[mi][ni][0], acc[mi][ni][1]);
            *(float2*)cp1 = make_float2(acc[mi][ni][2], acc[mi][ni][3]);
        }
    }
}

// =======================================================================
// conv + silu, writing bf16 hi/lo (and optionally fp32)
// =======================================================================
__global__ __launch_bounds__(256) void conv_silu_split(const float* __restrict__ in,
                                                       const float* __restrict__ w,
                                                       const float* __restrict__ bias,
                                                       __nv_bfloat16* __restrict__ oh,
                                                       __nv_bfloat16* __restrict__ ol,
                                                       float* __restrict__ of32,
                                                       int C, int npairs)
{
    int p = blockIdx.x * 256 + threadIdx.x;
    if (p >= npairs) return;
    const int Ch = C >> 1;
    int row = p / Ch;
    int c = (p - row * Ch) * 2;
    int l = row & (Ls - 1);
    size_t i = (size_t)row * C + c;
    float a0 = bias[c], a1 = bias[c + 1];
#pragma unroll
    for (int t = 0; t < 4; t++) {
        int ls = l + t - 3;
        if (ls >= 0) {
            a0 += w[c * 4 + t]       * in[i + (size_t)(t - 3) * C];
            a1 += w[(c + 1) * 4 + t] * in[i + 1 + (size_t)(t - 3) * C];
        }
    }
    a0 = a0 / (1.f + expf(-a0));
    a1 = a1 / (1.f + expf(-a1));
    if (of32) { of32[i] = a0; of32[i + 1] = a1; }
    uint32_t h, lo;
    split2(a0, a1, h, lo);
    ((uint32_t*)oh)[i >> 1] = h;
    ((uint32_t*)ol)[i >> 1] = lo;
}

// =======================================================================
// attention MMA kernels
// =======================================================================

// kvT[z][e][d] = sum_n vT[e,n] * (kdec(n) * kT[d,n])   (fp32 out)
__global__ __launch_bounds__(256, 1) void kvloc_mma(const float* __restrict__ slope)
{
    extern __shared__ char sm[];
    const uint32_t sbase = smem_u32(sm);
    const int tid = threadIdx.x, wid = tid >> 5, lane = tid & 31;
    const int z = blockIdx.z;
    const int b = z / (Hh * NB), h = (z / NB) % Hh, c = z % NB, hk = h >> 1;
    const float s = slope[h];
    const int m0 = blockIdx.y * 128, n0 = blockIdx.x * 128;   // m over e, n over d
    const int wm = (wid & 1) * 64, wn = (wid >> 1) * 32;
    const int t4 = lane & 3, tq = lane >> 2;
    const int fr = tid >> 3, fc = tid & 7;

    const __nv_bfloat16* Avh = g_vTh + ((size_t)(b * 8 + hk) * Dd + m0) * Ls + c * BLK;
    const __nv_bfloat16* Avl = g_vTl + ((size_t)(b * 8 + hk) * Dd + m0) * Ls + c * BLK;
    const float* BkT = g_kT + ((size_t)(b * 8 + hk) * Dd + n0) * Ls + c * BLK;
    const float ek = expf(s);

    float acc[4][4][4] = {};

#define FILLKV(st, buf) do {                                                              \
    const uint32_t sb = sbase + (buf) * STAGE_B;                                          \
    char* smb = sm + (buf) * STAGE_B;                                                     \
    const int k0 = (st) * 64;                                                             \
    fill_pair(sb + SA_H, sb + SA_L, Avh + k0, Avl + k0, Ls, fr, fc);                      \
    float kd0 = expf(-s * (float)(255 - (k0 + fc * 8)));                                  \
    fill_f32_decay(smb + SB_H, smb + SB_L, BkT + k0, Ls, fr, fc, kd0, ek);                \
} while (0)

    FILLKV(0, 0); CPCOMMIT();
    FILLKV(1, 1); CPCOMMIT();
    for (int st = 0; st < 4; st++) {
        CPWAIT1();
        __syncthreads();
        stage_mma(sbase + (st & 1) * STAGE_B, acc, wm, wn, tq, t4);
        __syncthreads();
        if (st + 2 < 4) FILLKV(st + 2, st & 1);
        CPCOMMIT();
    }
#undef FILLKV

    float* op = g_kv + (size_t)z * 65536;
#pragma unroll
    for (int mi = 0; mi < 4; mi++) {
        const int mA = m0 + wm + mi * 16 + tq, mB = mA + 8;
#pragma unroll
        for (int ni = 0; ni < 4; ni++) {
            const int cn = n0 + wn + ni * 8 + t4 * 2;
            *(float2*)(op + (size_t)mA * 256 + cn) = make_float2(acc[mi][ni][0], acc[mi][ni][1]);
            *(float2*)(op + (size_t)mB * 256 + cn) = make_float2(acc[mi][ni][2], acc[mi][ni][3]);
        }
    }
}

// exclusive decay prefix over chunks (fp32 in, bf16 hi/lo out)
__global__ __launch_bounds__(256) void kvprefix_split(const float* __restrict__ slope)
{
    const int pidx = blockIdx.x * 256 + threadIdx.x;   // Bb*Hh*32768 threads
    const int bh = pidx >> 15;
    const int off = (pidx & 32767) * 2;
    const int h = bh % Hh;
    const float bdec = expf(-slope[h] * (float)BLK);
    const float* p = g_kv + (size_t)bh * NB * 65536 + off;
    __nv_bfloat16* oh = g_kvTh + (size_t)bh * NB * 65536 + off;
    __nv_bfloat16* ol = g_kvTl + (size_t)bh * NB * 65536 + off;
    float a0 = 0.f, a1 = 0.f;
#pragma unroll
    for (int c = 0; c < NB; c++) {
        float2 loc = *(const float2*)(p + (size_t)c * 65536);
        uint32_t hh, ll;
        split2(a0, a1, hh, ll);
        *(uint32_t*)(oh + (size_t)c * 65536) = hh;
        *(uint32_t*)(ol + (size_t)c * 65536) = ll;
        a0 = a0 * bdec + loc.x;
        a1 = a1 * bdec + loc.y;
    }
}

// sc[z][m][n] = mask/decay( q[m,:]·k[n,:] ), split to bf16 hi/lo
__global__ __launch_bounds__(256, 1) void sc_mma(const float* __restrict__ slope)
{
    extern __shared__ char sm[];
    const uint32_t sbase = smem_u32(sm);
    const int tid = threadIdx.x, wid = tid >> 5, lane = tid & 31;
    const int z = blockIdx.z;
    const int b = z / (Hh * NB), h = (z / NB) % Hh, c = z % NB, hk = h >> 1;
    const float s = slope[h];
    const int m0 = blockIdx.y * 128, n0 = blockIdx.x * 128;
    const int wm = (wid & 1) * 64, wn = (wid >> 1) * 32;
    const int t4 = lane & 3, tq = lane >> 2;
    const int fr = tid >> 3, fc = tid & 7;

    const __nv_bfloat16* Ah = g_qh + (size_t)(b * Ls + c * BLK + m0) * HD + h * Dd;
    const __nv_bfloat16* Al = g_ql + (size_t)(b * Ls + c * BLK + m0) * HD + h * Dd;
    const __nv_bfloat16* Bh = g_kh + (size_t)(b * Ls + c * BLK + n0) * KD + hk * Dd;
    const __nv_bfloat16* Bl = g_kl + (size_t)(b * Ls + c * BLK + n0) * KD + hk * Dd;

    float acc[4][4][4] = {};

#define FILLSC(st, buf) do {                                                              \
    const uint32_t sb = sbase + (buf) * STAGE_B;                                          \
    const int k0 = (st) * 64;                                                             \
    fill_pair(sb + SA_H, sb + SA_L, Ah + k0, Al + k0, HD, fr, fc);                        \
    fill_pair(sb + SB_H, sb + SB_L, Bh + k0, Bl + k0, KD, fr, fc);                        \
} while (0)

    FILLSC(0, 0); CPCOMMIT();
    FILLSC(1, 1); CPCOMMIT();
    for (int st = 0; st < 4; st++) {
        CPWAIT1();
        __syncthreads();
        stage_mma(sbase + (st & 1) * STAGE_B, acc, wm, wn, tq, t4);
        __syncthreads();
        if (st + 2 < 4) FILLSC(st + 2, st & 1);
        CPCOMMIT();
    }
#undef FILLSC

    __nv_bfloat16* sh = g_sch + (size_t)z * 65536;
    __nv_bfloat16* sl = g_scl + (size_t)z * 65536;
#pragma unroll
    for (int mi = 0; mi < 4; mi++) {
        const int mA = m0 + wm + mi * 16 + tq, mB = mA + 8;
#pragma unroll
        for (int ni = 0; ni < 4; ni++) {
            const int cn = n0 + wn + ni * 8 + t4 * 2;
            float v0 = (mA >= cn)     ? acc[mi][ni][0] * expf(-s * (float)(mA - cn))     : 0.f;
            float v1 = (mA >= cn + 1) ? acc[mi][ni][1] * expf(-s * (float)(mA - cn - 1)) : 0.f;
            float v2 = (mB >= cn)     ? acc[mi][ni][2] * expf(-s * (float)(mB - cn))     : 0.f;
            float v3 = (mB >= cn + 1) ? acc[mi][ni][3] * expf(-s * (float)(mB - cn - 1)) : 0.f;
            uint32_t hh, ll;
            split2(v0, v1, hh, ll);
            *(uint32_t*)(sh + (size_t)mA * 256 + cn) = hh;
            *(uint32_t*)(sl + (size_t)mA * 256 + cn) = ll;
            split2(v2, v3, hh, ll);
            *(uint32_t*)(sh + (size_t)mB * 256 + cn) = hh;
            *(uint32_t*)(sl + (size_t)mB * 256 + cn) = ll;
        }
    }
}

// o[m,e] = qdec(m) * (q @ kvT^T) + sc @ vT^T    (fp32 out)
__global__ __launch_bounds__(256, 1) void out_mma(const float* __restrict__ slope)
{
    extern __shared__ char sm[];
    const uint32_t sbase = smem_u32(sm);
    const int tid = threadIdx.x, wid = tid >> 5, lane = tid & 31;
    const int z = blockIdx.z;
    const int b = z / (Hh * NB), h = (z / NB) % Hh, c = z % NB, hk = h >> 1;
    const float s = slope[h];
    const int m0 = blockIdx.y * 128, n0 = blockIdx.x * 128;   // n over e
    const int wm = (wid & 1) * 64, wn = (wid >> 1) * 32;
    const int t4 = lane & 3, tq = lane >> 2;
    const int fr = tid >> 3, fc = tid & 7;

    float acc[4][4][4] = {};

    // ---- phase 1: q @ kvT^T (contract d) ----
    {
        const __nv_bfloat16* Ah = g_qh + (size_t)(b * Ls + c * BLK + m0) * HD + h * Dd;
        const __nv_bfloat16* Al = g_ql + (size_t)(b * Ls + c * BLK + m0) * HD + h * Dd;
        const __nv_bfloat16* Bh = g_kvTh + (size_t)z * 65536 + (size_t)n0 * 256;
        const __nv_bfloat16* Bl = g_kvTl + (size_t)z * 65536 + (size_t)n0 * 256;
#define FILLO1(st, buf) do {                                                              \
    const uint32_t sb = sbase + (buf) * STAGE_B;                                          \
    const int k0 = (st) * 64;                                                             \
    fill_pair(sb + SA_H, sb + SA_L, Ah + k0, Al + k0, HD, fr, fc);                        \
    fill_pair(sb + SB_H, sb + SB_L, Bh + k0, Bl + k0, 256, fr, fc);                       \
} while (0)
        FILLO1(0, 0); CPCOMMIT();
        FILLO1(1, 1); CPCOMMIT();
        for (int st = 0; st < 4; st++) {
            CPWAIT1();
            __syncthreads();
            stage_mma(sbase + (st & 1) * STAGE_B, acc, wm, wn, tq, t4);
            __syncthreads();
            if (st + 2 < 4) FILLO1(st + 2, st & 1);
            CPCOMMIT();
        }
#undef FILLO1
    }

    // scale phase-1 contribution by qdec(row)
#pragma unroll
    for (int mi = 0; mi < 4; mi++) {
        const int mA = m0 + wm + mi * 16 + tq;
        const float qd0 = expf(-s * (float)(mA + 1));
        const float qd1 = expf(-s * (float)(mA + 9));
#pragma unroll
        for (int ni = 0; ni < 4; ni++) {
            acc[mi][ni][0] *= qd0;
            acc[mi][ni][1] *= qd0;
            acc[mi][ni][2] *= qd1;
            acc[mi][ni][3] *= qd1;
        }
    }

    // ---- phase 2: sc @ vT^T (contract n) ----
    {
        const __nv_bfloat16* Ah = g_sch + (size_t)z * 65536 + (size_t)m0 * 256;
        const __nv_bfloat16* Al = g_scl + (size_t)z * 65536 + (size_t)m0 * 256;
        const __nv_bfloat16* Bh = g_vTh + ((size_t)(b * 8 + hk) * Dd + n0) * Ls + c * BLK;
        const __nv_bfloat16* Bl = g_vTl + ((size_t)(b * 8 + hk) * Dd + n0) * Ls + c * BLK;
#define FILLO2(st, buf) do {                                                              \
    const uint32_t sb = sbase + (buf) * STAGE_B;                                          \
    const int k0 = (st) * 64;                                                             \
    fill_pair(sb + SA_H, sb + SA_L, Ah + k0, Al + k0, 256, fr, fc);                       \
    fill_pair(sb + SB_H, sb + SB_L, Bh + k0, Bl + k0, Ls, fr, fc);                        \
} while (0)
        FILLO2(0, 0); CPCOMMIT();
        FILLO2(1, 1); CPCOMMIT();
        for (int st = 0; st < 4; st++) {
            CPWAIT1();
            __syncthreads();
            stage_mma(sbase + (st & 1) * STAGE_B, acc, wm, wn, tq, t4);
            __syncthreads();
            if (st + 2 < 4) FILLO2(st + 2, st & 1);
            CPCOMMIT();
        }
#undef FILLO2
    }

    float* op = g_o + (size_t)(b * Ls + c * BLK) * HD + h * Dd;
#pragma unroll
    for (int mi = 0; mi < 4; mi++) {
        const int mA = m0 + wm + mi * 16 + tq, mB = mA + 8;
#pragma unroll
        for (int ni = 0; ni < 4; ni++) {
            const int cn = n0 + wn + ni * 8 + t4 * 2;
            *(float2*)(op + (size_t)mA * HD + cn) = make_float2(acc[mi][ni][0], acc[mi][ni][1]);
            *(float2*)(op + (size_t)mB * HD + cn) = make_float2(acc[mi][ni][2], acc[mi][ni][3]);
        }
    }
}

// ---------------- SimpleRMSNorm + bf16 hi/lo split output ----------------
__global__ __launch_bounds__(256) void rmsnorm_split_kernel()
{
    const int row = blockIdx.x;
    const float* p = g_o + (size_t)row * HD;
    __nv_bfloat16* oh = g_oh + (size_t)row * HD;
    __nv_bfloat16* ol = g_ol + (size_t)row * HD;
    const int tid = threadIdx.x;
    float ss = 0.f;
    for (int i = tid; i < HD; i += 256) {
        float v = p[i];
        ss += v * v;
    }
#pragma unroll
    for (int off = 16; off > 0; off >>= 1) ss += __shfl_xor_sync(0xffffffffu, ss, off);
    __shared__ float red[8];
    __shared__ float scale_s;
    if ((tid & 31) == 0) red[tid >> 5] = ss;
    __syncthreads();
    if (tid == 0) {
        float tot = 0.f;
#pragma unroll
        for (int w = 0; w < 8; w++) tot += red[w];
        scale_s = rsqrtf(tot / (float)HD + 1e-6f);
    }
    __syncthreads();
    const float sc = scale_s;
    for (int i = tid * 2; i < HD; i += 512) {
        float v0 = p[i] * sc, v1 = p[i + 1] * sc;
        uint32_t h, l;
        split2(v0, v1, h, l);
        *(uint32_t*)(oh + i) = h;
        *(uint32_t*)(ol + i) = l;
    }
}

// ---------------- launcher ----------------
extern "C" void kernel_launch(void* const* d_in, const int* in_sizes, int n_in,
                              void* d_out, int out_size)
{
    const float* x     = (const float*)d_in[0];
    const float* Wq    = (const float*)d_in[1];
    const float* Wk    = (const float*)d_in[2];
    const float* Wv    = (const float*)d_in[3];
    const float* Wo    = (const float*)d_in[4];
    const float* cqw   = (const float*)d_in[5];
    const float* cqb   = (const float*)d_in[6];
    const float* ckw   = (const float*)d_in[7];
    const float* ckb   = (const float*)d_in[8];
    const float* slope = (const float*)d_in[9];
    float* out = (float*)d_out;

    float *qpre, *kpre, *k, *v, *kT;
    __nv_bfloat16 *xh, *xl, *wth, *wtl, *oh, *ol, *qh, *ql, *kh, *kl, *vth, *vtl;
    cudaGetSymbolAddress((void**)&qpre, g_qpre);
    cudaGetSymbolAddress((void**)&kpre, g_kpre);
    cudaGetSymbolAddress((void**)&k,    g_k);
    cudaGetSymbolAddress((void**)&v,    g_v);
    cudaGetSymbolAddress((void**)&kT,   g_kT);
    cudaGetSymbolAddress((void**)&xh,   g_xh);
    cudaGetSymbolAddress((void**)&xl,   g_xl);
    cudaGetSymbolAddress((void**)&wth,  g_wth);
    cudaGetSymbolAddress((void**)&wtl,  g_wtl);
    cudaGetSymbolAddress((void**)&oh,   g_oh);
    cudaGetSymbolAddress((void**)&ol,   g_ol);
    cudaGetSymbolAddress((void**)&qh,   g_qh);
    cudaGetSymbolAddress((void**)&ql,   g_ql);
    cudaGetSymbolAddress((void**)&kh,   g_kh);
    cudaGetSymbolAddress((void**)&kl,   g_kl);
    cudaGetSymbolAddress((void**)&vth,  g_vTh);
    cudaGetSymbolAddress((void**)&vtl,  g_vTl);

    float* o;
    cudaGetSymbolAddress((void**)&o, g_o);

    cudaFuncSetAttribute(hgemm,     cudaFuncAttributeMaxDynamicSharedMemorySize, HG_SMEM);
    cudaFuncSetAttribute(kvloc_mma, cudaFuncAttributeMaxDynamicSharedMemorySize, HG_SMEM);
    cudaFuncSetAttribute(sc_mma,    cudaFuncAttributeMaxDynamicSharedMemorySize, HG_SMEM);
    cudaFuncSetAttribute(out_mma,   cudaFuncAttributeMaxDynamicSharedMemorySize, HG_SMEM);

    const int M = Bb * Ls;   // 4096

    // split x once
    convsplit<<<(M * HIDd / 4 + 255) / 256, 256>>>(x, xh, xl, M * HIDd / 4);

    // projections
    tsplit<<<dim3(HD / 32, HIDd / 32), 256>>>(Wq, wth, wtl, HIDd, HD);
    hgemm<<<dim3(HD / 128, M / 128), 256, HG_SMEM>>>(xh, xl, wth, wtl, qpre, M, HD, HIDd);
    tsplit<<<dim3(KD / 32, HIDd / 32), 256>>>(Wk, wth, wtl, HIDd, KD);
    hgemm<<<dim3(KD / 128, M / 128), 256, HG_SMEM>>>(xh, xl, wth, wtl, kpre, M, KD, HIDd);
    tsplit<<<dim3(KD / 32, HIDd / 32), 256>>>(Wv, wth, wtl, HIDd, KD);
    hgemm<<<dim3(KD / 128, M / 128), 256, HG_SMEM>>>(xh, xl, wth, wtl, v, M, KD, HIDd);

    // conv + silu, split to bf16 hi/lo (k keeps fp32 for transpose)
    conv_silu_split<<<(M * HD / 2 + 255) / 256, 256>>>(qpre, cqw, cqb, qh, ql, nullptr, HD, M * HD / 2);
    conv_silu_split<<<(M * KD / 2 + 255) / 256, 256>>>(kpre, ckw, ckb, kh, kl, k, KD, M * KD / 2);

    // transposes for n-contraction GEMMs
    trans_f32  <<<dim3(Ls / 32, Dd / 32, 16), 256>>>(k, kT);
    trans_split<<<dim3(Ls / 32, Dd / 32, 16), 256>>>(v, vth, vtl);

    // lightning attention (all HMMA)
    kvloc_mma<<<dim3(2, 2, Bb * Hh * NB), 256, HG_SMEM>>>(slope);
    kvprefix_split<<<(Bb * Hh * 32768) / 256, 256>>>(slope);
    sc_mma<<<dim3(2, 2, Bb * Hh * NB), 256, HG_SMEM>>>(slope);
    out_mma<<<dim3(2, 2, Bb * Hh * NB), 256, HG_SMEM>>>(slope);

    // norm + split + output projection
    rmsnorm_split_kernel<<<M, 256>>>();
    tsplit<<<dim3(HIDd / 32, HD / 32), 256>>>(Wo, wth, wtl, HD, HIDd);
    hgemm<<<dim3(HIDd / 128, M / 128), 256, HG_SMEM>>>(oh, ol, wth, wtl, out, M, HIDd, HD);
}

// round 6
// speedup vs baseline: 3.3374x; 1.0755x over previous
#include <cuda_runtime.h>
#include <cuda_bf16.h>
#include <cstdint>

#define Bb   2
#define Ls   2048
#define Hh   16
#define Dd   256
#define HD   4096   // H*D
#define KD   2048   // HKV*D
#define HIDd 2048
#define NB   8
#define BLK  256
#define NQKV 8192   // HD + KD + KD

// ---------------- scratch (static device memory; no allocs) ----------------
static __device__ __align__(128) float g_qkvpre[Bb * Ls * NQKV];   // fused qkv pre-activation
static __device__ __align__(128) float g_kf  [Bb * Ls * KD];       // k fp32 post-conv
static __device__ __align__(128) float g_kv  [Bb * Hh * NB * Dd * Dd];
static __device__ __align__(128) float g_o   [Bb * Ls * HD];
static __device__ __align__(128) float g_kT  [16 * Dd * Ls];

static __device__ __align__(128) __nv_bfloat16 g_xh   [Bb * Ls * HIDd];
static __device__ __align__(128) __nv_bfloat16 g_xl   [Bb * Ls * HIDd];
static __device__ __align__(128) __nv_bfloat16 g_wqkvh[NQKV * HIDd];
static __device__ __align__(128) __nv_bfloat16 g_wqkvl[NQKV * HIDd];
static __device__ __align__(128) __nv_bfloat16 g_woh  [HIDd * HD];
static __device__ __align__(128) __nv_bfloat16 g_wol  [HIDd * HD];
static __device__ __align__(128) __nv_bfloat16 g_oh   [Bb * Ls * HD];
static __device__ __align__(128) __nv_bfloat16 g_ol   [Bb * Ls * HD];
static __device__ __align__(128) __nv_bfloat16 g_qh   [Bb * Ls * HD];
static __device__ __align__(128) __nv_bfloat16 g_ql   [Bb * Ls * HD];
static __device__ __align__(128) __nv_bfloat16 g_kh   [Bb * Ls * KD];
static __device__ __align__(128) __nv_bfloat16 g_kl   [Bb * Ls * KD];
static __device__ __align__(128) __nv_bfloat16 g_vTh  [16 * Dd * Ls];
static __device__ __align__(128) __nv_bfloat16 g_vTl  [16 * Dd * Ls];
static __device__ __align__(128) __nv_bfloat16 g_kvTh [Bb * Hh * NB * Dd * Dd];
static __device__ __align__(128) __nv_bfloat16 g_kvTl [Bb * Hh * NB * Dd * Dd];
static __device__ __align__(128) __nv_bfloat16 g_sch  [Bb * Hh * NB * BLK * BLK];
static __device__ __align__(128) __nv_bfloat16 g_scl  [Bb * Hh * NB * BLK * BLK];

// =======================================================================
// helpers
// =======================================================================
__device__ __forceinline__ uint32_t smem_u32(const void* p) {
    uint32_t a;
    asm("{ .reg .u64 t; cvta.to.shared.u64 t, %1; cvt.u32.u64 %0, t; }" : "=r"(a) : "l"(p));
    return a;
}
__device__ __forceinline__ void split2(float x0, float x1, uint32_t& hi, uint32_t& lo) {
    __nv_bfloat16 h0 = __float2bfloat16_rn(x0);
    __nv_bfloat16 h1 = __float2bfloat16_rn(x1);
    float r0 = x0 - __bfloat162float(h0);
    float r1 = x1 - __bfloat162float(h1);
    __nv_bfloat162 hp; hp.x = h0; hp.y = h1;
    __nv_bfloat162 lp = __floats2bfloat162_rn(r0, r1);
    hi = *reinterpret_cast<uint32_t*>(&hp);
    lo = *reinterpret_cast<uint32_t*>(&lp);
}
#define CPA16(dst, src) asm volatile("cp.async.cg.shared.global [%0], [%1], 16;" :: "r"(dst), "l"(src))
#define CPCOMMIT()      asm volatile("cp.async.commit_group;" ::: "memory")
#define CPWAIT1()       asm volatile("cp.async.wait_group 1;" ::: "memory")
__device__ __forceinline__ uint32_t lds32(uint32_t a) {
    uint32_t v;
    asm volatile("ld.shared.b32 %0, [%1];" : "=r"(v) : "r"(a));
    return v;
}
__device__ __forceinline__ void mma16816(float* d, const uint32_t* a, const uint32_t* b) {
    asm volatile("mma.sync.aligned.m16n8k16.row.col.f32.bf16.bf16.f32 "
                 "{%0,%1,%2,%3}, {%4,%5,%6,%7}, {%8,%9}, {%0,%1,%2,%3};"
                 : "+f"(d[0]), "+f"(d[1]), "+f"(d[2]), "+f"(d[3])
                 : "r"(a[0]), "r"(a[1]), "r"(a[2]), "r"(a[3]), "r"(b[0]), "r"(b[1]));
}

// ---------- 128x128-tile layout (attention kernels) ----------
#define SA_H 0
#define SA_L 16384
#define SB_H 32768
#define SB_L 49152
#define STAGE_B 65536
#define HG_SMEM (2 * STAGE_B)

__device__ __forceinline__ void stage_mma(uint32_t sb, float acc[4][4][4],
                                          int wm, int wn, int tq, int t4)
{
#pragma unroll
    for (int kk = 0; kk < 4; kk++) {
        uint32_t ah[4][4], al[4][4], bh[4][2], bl[4][2];
#pragma unroll
        for (int mi = 0; mi < 4; mi++) {
            const int m = wm + mi * 16 + tq;
            const uint32_t e = (uint32_t)(m & 7);
            const uint32_t rp = sb + (uint32_t)(m * 128) + t4 * 4;
            const uint32_t o0 = (uint32_t)((2 * kk) ^ e) << 4;
            const uint32_t o1 = (uint32_t)((2 * kk + 1) ^ e) << 4;
            ah[mi][0] = lds32(rp + SA_H + o0);
            ah[mi][1] = lds32(rp + SA_H + o0 + 1024);
            ah[mi][2] = lds32(rp + SA_H + o1);
            ah[mi][3] = lds32(rp + SA_H + o1 + 1024);
            al[mi][0] = lds32(rp + SA_L + o0);
            al[mi][1] = lds32(rp + SA_L + o0 + 1024);
            al[mi][2] = lds32(rp + SA_L + o1);
            al[mi][3] = lds32(rp + SA_L + o1 + 1024);
        }
#pragma unroll
        for (int ni = 0; ni < 4; ni++) {
            const int n = wn + ni * 8 + tq;
            const uint32_t e = (uint32_t)(n & 7);
            const uint32_t rp = sb + (uint32_t)(n * 128) + t4 * 4;
            const uint32_t o0 = (uint32_t)((2 * kk) ^ e) << 4;
            const uint32_t o1 = (uint32_t)((2 * kk + 1) ^ e) << 4;
            bh[ni][0] = lds32(rp + SB_H + o0);
            bh[ni][1] = lds32(rp + SB_H + o1);
            bl[ni][0] = lds32(rp + SB_L + o0);
            bl[ni][1] = lds32(rp + SB_L + o1);
        }
#pragma unroll
        for (int mi = 0; mi < 4; mi++)
#pragma unroll
            for (int ni = 0; ni < 4; ni++) {
                mma16816(acc[mi][ni], ah[mi], bh[ni]);
                mma16816(acc[mi][ni], al[mi], bh[ni]);
                mma16816(acc[mi][ni], ah[mi], bl[ni]);
            }
    }
}

__device__ __forceinline__ void fill_pair(uint32_t sb_h, uint32_t sb_l,
                                          const __nv_bfloat16* gh, const __nv_bfloat16* gl,
                                          size_t stride, int fr, int fc)
{
#pragma unroll
    for (int i = 0; i < 4; i++) {
        int r = fr + 32 * i;
        uint32_t doff = (uint32_t)(r * 128 + ((fc ^ (r & 7)) << 4));
        size_t so = (size_t)r * stride + fc * 8;
        CPA16(sb_h + doff, gh + so);
        CPA16(sb_l + doff, gl + so);
    }
}

__device__ __forceinline__ void fill_f32_decay(char* smh, char* sml,
                                               const float* g, size_t stride,
                                               int fr, int fc, float kd0, float ek)
{
    float kd[8];
    kd[0] = kd0;
#pragma unroll
    for (int j = 1; j < 8; j++) kd[j] = kd[j - 1] * ek;
#pragma unroll
    for (int i = 0; i < 4; i++) {
        int r = fr + 32 * i;
        uint32_t doff = (uint32_t)(r * 128 + ((fc ^ (r & 7)) << 4));
        const float* sp = g + (size_t)r * stride + fc * 8;
        float4 u = *(const float4*)sp;
        float4 w = *(const float4*)(sp + 4);
        uint4 hi, lo;
        split2(u.x * kd[0], u.y * kd[1], hi.x, lo.x);
        split2(u.z * kd[2], u.w * kd[3], hi.y, lo.y);
        split2(w.x * kd[4], w.y * kd[5], hi.z, lo.z);
        split2(w.z * kd[6], w.w * kd[7], hi.w, lo.w);
        *(uint4*)(smh + doff) = hi;
        *(uint4*)(sml + doff) = lo;
    }
}

// =======================================================================
// hgemm2: 128(M) x 256(N) tile, BK=64, 2-stage — big projections
// =======================================================================
#define G2_SA_H 0
#define G2_SA_L 16384
#define G2_SB_H 32768
#define G2_SB_L 65536
#define G2_STAGE 98304
#define G2_SMEM (2 * G2_STAGE)

__global__ __launch_bounds__(256, 1) void hgemm2(const __nv_bfloat16* __restrict__ Ah,
                                                 const __nv_bfloat16* __restrict__ Al,
                                                 const __nv_bfloat16* __restrict__ Bh,
                                                 const __nv_bfloat16* __restrict__ Bl,
                                                 float* __restrict__ C,
                                                 int M, int N, int K)
{
    extern __shared__ char sm[];
    const uint32_t sbase = smem_u32(sm);
    const int tid = threadIdx.x, wid = tid >> 5, lane = tid & 31;
    const int m0 = blockIdx.y * 128, n0 = blockIdx.x * 256;
    const int wm = (wid & 1) * 64, wn = (wid >> 1) * 64;
    const int t4 = lane & 3, tq = lane >> 2;
    const int fr = tid >> 3, fc = tid & 7;

    float acc[4][8][4];
#pragma unroll
    for (int a = 0; a < 4; a++)
#pragma unroll
        for (int b = 0; b < 8; b++)
#pragma unroll
            for (int c = 0; c < 4; c++) acc[a][b][c] = 0.f;

#define FILL2(s, buf) do {                                                                \
    const uint32_t sb = sbase + (buf) * G2_STAGE;                                         \
    const int k0 = (s) * 64;                                                              \
    _Pragma("unroll")                                                                     \
    for (int i = 0; i < 4; i++) {                                                         \
        int r = fr + 32 * i;                                                              \
        uint32_t doff = (uint32_t)(r * 128 + ((fc ^ (r & 7)) << 4));                      \
        size_t so = (size_t)(m0 + r) * K + k0 + fc * 8;                                   \
        CPA16(sb + G2_SA_H + doff, Ah + so);                                              \
        CPA16(sb + G2_SA_L + doff, Al + so);                                              \
    }                                                                                     \
    _Pragma("unroll")                                                                     \
    for (int i = 0; i < 8; i++) {                                                         \
        int r = fr + 32 * i;                                                              \
        uint32_t doff = (uint32_t)(r * 128 + ((fc ^ (r & 7)) << 4));                      \
        size_t so = (size_t)(n0 + r) * K + k0 + fc * 8;                                   \
        CPA16(sb + G2_SB_H + doff, Bh + so);                                              \
        CPA16(sb + G2_SB_L + doff, Bl + so);                                              \
    }                                                                                     \
} while (0)

    const int S = K / 64;
    FILL2(0, 0); CPCOMMIT();
    FILL2(1, 1); CPCOMMIT();

    for (int s = 0; s < S; s++) {
        CPWAIT1();
        __syncthreads();
        const uint32_t sb = sbase + (s & 1) * G2_STAGE;
#pragma unroll
        for (int kk = 0; kk < 4; kk++) {
            uint32_t ah[4][4], al[4][4], bh[8][2], bl[8][2];
#pragma unroll
            for (int mi = 0; mi < 4; mi++) {
                const int m = wm + mi * 16 + tq;
                const uint32_t e = (uint32_t)(m & 7);
                const uint32_t rp = sb + (uint32_t)(m * 128) + t4 * 4;
                const uint32_t o0 = (uint32_t)((2 * kk) ^ e) << 4;
                const uint32_t o1 = (uint32_t)((2 * kk + 1) ^ e) << 4;
                ah[mi][0] = lds32(rp + G2_SA_H + o0);
                ah[mi][1] = lds32(rp + G2_SA_H + o0 + 1024);
                ah[mi][2] = lds32(rp + G2_SA_H + o1);
                ah[mi][3] = lds32(rp + G2_SA_H + o1 + 1024);
                al[mi][0] = lds32(rp + G2_SA_L + o0);
                al[mi][1] = lds32(rp + G2_SA_L + o0 + 1024);
                al[mi][2] = lds32(rp + G2_SA_L + o1);
                al[mi][3] = lds32(rp + G2_SA_L + o1 + 1024);
            }
#pragma unroll
            for (int ni = 0; ni < 8; ni++) {
                const int n = wn + ni * 8 + tq;
                const uint32_t e = (uint32_t)(n & 7);
                const uint32_t rp = sb + (uint32_t)(n * 128) + t4 * 4;
                const uint32_t o0 = (uint32_t)((2 * kk) ^ e) << 4;
                const uint32_t o1 = (uint32_t)((2 * kk + 1) ^ e) << 4;
                bh[ni][0] = lds32(rp + G2_SB_H + o0);
                bh[ni][1] = lds32(rp + G2_SB_H + o1);
                bl[ni][0] = lds32(rp + G2_SB_L + o0);
                bl[ni][1] = lds32(rp + G2_SB_L + o1);
            }
#pragma unroll
            for (int mi = 0; mi < 4; mi++)
#pragma unroll
                for (int ni = 0; ni < 8; ni++) {
                    mma16816(acc[mi][ni], ah[mi], bh[ni]);
                    mma16816(acc[mi][ni], al[mi], bh[ni]);
                    mma16816(acc[mi][ni], ah[mi], bl[ni]);
                }
        }
        __syncthreads();
        if (s + 2 < S) FILL2(s + 2, s & 1);
        CPCOMMIT();
    }
#undef FILL2

#pragma unroll
    for (int mi = 0; mi < 4; mi++) {
        const int m = m0 + wm + mi * 16 + tq;
#pragma unroll
        for (int ni = 0; ni < 8; ni++) {
            const int n = n0 + wn + ni * 8 + t4 * 2;
            *(float2*)(C + (size_t)m * N + n)       = make_float2(acc[mi][ni][0], acc[mi][ni][1]);
            *(float2*)(C + (size_t)(m + 8) * N + n) = make_float2(acc[mi][ni][2], acc[mi][ni][3]);
        }
    }
}

// =======================================================================
// convert kernels
// =======================================================================
__global__ __launch_bounds__(256) void convsplit(const float* __restrict__ in,
                                                 __nv_bfloat16* __restrict__ hi,
                                                 __nv_bfloat16* __restrict__ lo, int n4)
{
    int i = blockIdx.x * 256 + threadIdx.x;
    if (i >= n4) return;
    float4 v = ((const float4*)in)[i];
    uint2 h, l;
    split2(v.x, v.y, h.x, l.x);
    split2(v.z, v.w, h.y, l.y);
    ((uint2*)hi)[i] = h;
    ((uint2*)lo)[i] = l;
}

__global__ __launch_bounds__(256) void tsplit(const float* __restrict__ W,
                                              __nv_bfloat16* __restrict__ th,
                                              __nv_bfloat16* __restrict__ tl,
                                              int Kd, int Nd)
{
    __shared__ float t[32][33];
    const int bxn = blockIdx.x * 32;
    const int byk = blockIdx.y * 32;
    const int x = threadIdx.x & 31, y = threadIdx.x >> 5;
#pragma unroll
    for (int j = 0; j < 4; j++)
        t[y + 8 * j][x] = W[(size_t)(byk + y + 8 * j) * Nd + bxn + x];
    __syncthreads();
    const int n = bxn + x;
    float v0 = t[y * 4 + 0][x];
    float v1 = t[y * 4 + 1][x];
    float v2 = t[y * 4 + 2][x];
    float v3 = t[y * 4 + 3][x];
    uint2 h, l;
    split2(v0, v1, h.x, l.x);
    split2(v2, v3, h.y, l.y);
    size_t off = ((size_t)n * Kd + byk + y * 4) >> 2;
    ((uint2*)th)[off] = h;
    ((uint2*)tl)[off] = l;
}

// transpose fp32 [b,l,(cols)] -> fp32 [b*8+hk][d][l]  (from g_kf, stride KD)
__global__ __launch_bounds__(256) void trans_f32(const float* __restrict__ in,
                                                 float* __restrict__ out)
{
    __shared__ float t[32][33];
    const int bk = blockIdx.z;
    const int b = bk >> 3, hk = bk & 7;
    const int l0 = blockIdx.x * 32, d0 = blockIdx.y * 32;
    const int x = threadIdx.x & 31, y = threadIdx.x >> 5;
#pragma unroll
    for (int j = 0; j < 4; j++)
        t[y + 8 * j][x] = in[(size_t)(b * Ls + l0 + y + 8 * j) * KD + hk * Dd + d0 + x];
    __syncthreads();
#pragma unroll
    for (int j = 0; j < 4; j++) {
        int d = d0 + y + 8 * j;
        out[((size_t)bk * Dd + d) * Ls + l0 + x] = t[x][y + 8 * j];
    }
}

// transpose fp32 strided input -> bf16 hi/lo [b*8+hk][d][l]
__global__ __launch_bounds__(256) void trans_split(const float* __restrict__ in,
                                                   int instride, int colbase,
                                                   __nv_bfloat16* __restrict__ oth,
                                                   __nv_bfloat16* __restrict__ otl)
{
    __shared__ float t[32][33];
    const int bk = blockIdx.z;
    const int b = bk >> 3, hk = bk & 7;
    const int l0 = blockIdx.x * 32, d0 = blockIdx.y * 32;
    const int x = threadIdx.x & 31, y = threadIdx.x >> 5;
#pragma unroll
    for (int j = 0; j < 4; j++)
        t[y + 8 * j][x] = in[(size_t)(b * Ls + l0 + y + 8 * j) * instride + colbase + hk * Dd + d0 + x];
    __syncthreads();
    const int x2 = threadIdx.x & 15, yy = threadIdx.x >> 4;
#pragma unroll
    for (int j = 0; j < 2; j++) {
        int d = d0 + yy + 16 * j;
        float v0 = t[x2 * 2][yy + 16 * j];
        float v1 = t[x2 * 2 + 1][yy + 16 * j];
        uint32_t h, l;
        split2(v0, v1, h, l);
        size_t off = (((size_t)bk * Dd + d) * Ls + l0 + x2 * 2) >> 1;
        ((uint32_t*)oth)[off] = h;
        ((uint32_t*)otl)[off] = l;
    }
}

// conv + silu with strided input; outputs compact [row][C] bf16 hi/lo (+ optional fp32)
__global__ __launch_bounds__(256) void conv_silu_split(const float* __restrict__ in,
                                                       int instride,
                                                       const float* __restrict__ w,
                                                       const float* __restrict__ bias,
                                                       __nv_bfloat16* __restrict__ oh,
                                                       __nv_bfloat16* __restrict__ ol,
                                                       float* __restrict__ of32,
                                                       int C, int npairs)
{
    int p = blockIdx.x * 256 + threadIdx.x;
    if (p >= npairs) return;
    const int Ch = C >> 1;
    int row = p / Ch;
    int c = (p - row * Ch) * 2;
    int l = row & (Ls - 1);
    const float* ip = in + (size_t)row * instride + c;
    float a0 = bias[c], a1 = bias[c + 1];
#pragma unroll
    for (int t = 0; t < 4; t++) {
        int ls = l + t - 3;
        if (ls >= 0) {
            a0 += w[c * 4 + t]       * ip[(ptrdiff_t)(t - 3) * instride];
            a1 += w[(c + 1) * 4 + t] * ip[(ptrdiff_t)(t - 3) * instride + 1];
        }
    }
    a0 = a0 / (1.f + expf(-a0));
    a1 = a1 / (1.f + expf(-a1));
    size_t oidx = (size_t)row * C + c;
    if (of32) { of32[oidx] = a0; of32[oidx + 1] = a1; }
    uint32_t h, lo;
    split2(a0, a1, h, lo);
    ((uint32_t*)oh)[oidx >> 1] = h;
    ((uint32_t*)ol)[oidx >> 1] = lo;
}

// =======================================================================
// attention MMA kernels (128x128 tiles, unchanged from R4)
// =======================================================================
__global__ __launch_bounds__(256, 1) void kvloc_mma(const float* __restrict__ slope)
{
    extern __shared__ char sm[];
    const uint32_t sbase = smem_u32(sm);
    const int tid = threadIdx.x, wid = tid >> 5, lane = tid & 31;
    const int z = blockIdx.z;
    const int b = z / (Hh * NB), h = (z / NB) % Hh, c = z % NB, hk = h >> 1;
    const float s = slope[h];
    const int m0 = blockIdx.y * 128, n0 = blockIdx.x * 128;
    const int wm = (wid & 1) * 64, wn = (wid >> 1) * 32;
    const int t4 = lane & 3, tq = lane >> 2;
    const int fr = tid >> 3, fc = tid & 7;

    const __nv_bfloat16* Avh = g_vTh + ((size_t)(b * 8 + hk) * Dd + m0) * Ls + c * BLK;
    const __nv_bfloat16* Avl = g_vTl + ((size_t)(b * 8 + hk) * Dd + m0) * Ls + c * BLK;
    const float* BkT = g_kT + ((size_t)(b * 8 + hk) * Dd + n0) * Ls + c * BLK;
    const float ek = expf(s);

    float acc[4][4][4] = {};

#define FILLKV(st, buf) do {                                                              \
    const uint32_t sb = sbase + (buf) * STAGE_B;                                          \
    char* smb = sm + (buf) * STAGE_B;                                                     \
    const int k0 = (st) * 64;                                                             \
    fill_pair(sb + SA_H, sb + SA_L, Avh + k0, Avl + k0, Ls, fr, fc);                      \
    float kd0 = expf(-s * (float)(255 - (k0 + fc * 8)));                                  \
    fill_f32_decay(smb + SB_H, smb + SB_L, BkT + k0, Ls, fr, fc, kd0, ek);                \
} while (0)

    FILLKV(0, 0); CPCOMMIT();
    FILLKV(1, 1); CPCOMMIT();
    for (int st = 0; st < 4; st++) {
        CPWAIT1();
        __syncthreads();
        stage_mma(sbase + (st & 1) * STAGE_B, acc, wm, wn, tq, t4);
        __syncthreads();
        if (st + 2 < 4) FILLKV(st + 2, st & 1);
        CPCOMMIT();
    }
#undef FILLKV

    float* op = g_kv + (size_t)z * 65536;
#pragma unroll
    for (int mi = 0; mi < 4; mi++) {
        const int mA = m0 + wm + mi * 16 + tq, mB = mA + 8;
#pragma unroll
        for (int ni = 0; ni < 4; ni++) {
            const int cn = n0 + wn + ni * 8 + t4 * 2;
            *(float2*)(op + (size_t)mA * 256 + cn) = make_float2(acc[mi][ni][0], acc[mi][ni][1]);
            *(float2*)(op + (size_t)mB * 256 + cn) = make_float2(acc[mi][ni][2], acc[mi][ni][3]);
        }
    }
}

__global__ __launch_bounds__(256) void kvprefix_split(const float* __restrict__ slope)
{
    const int pidx = blockIdx.x * 256 + threadIdx.x;
    const int bh = pidx >> 15;
    const int off = (pidx & 32767) * 2;
    const int h = bh % Hh;
    const float bdec = expf(-slope[h] * (float)BLK);
    const float* p = g_kv + (size_t)bh * NB * 65536 + off;
    __nv_bfloat16* oh = g_kvTh + (size_t)bh * NB * 65536 + off;
    __nv_bfloat16* ol = g_kvTl + (size_t)bh * NB * 65536 + off;
    float a0 = 0.f, a1 = 0.f;
#pragma unroll
    for (int c = 0; c < NB; c++) {
        float2 loc = *(const float2*)(p + (size_t)c * 65536);
        uint32_t hh, ll;
        split2(a0, a1, hh, ll);
        *(uint32_t*)(oh + (size_t)c * 65536) = hh;
        *(uint32_t*)(ol + (size_t)c * 65536) = ll;
        a0 = a0 * bdec + loc.x;
        a1 = a1 * bdec + loc.y;
    }
}

__global__ __launch_bounds__(256, 1) void sc_mma(const float* __restrict__ slope)
{
    extern __shared__ char sm[];
    const uint32_t sbase = smem_u32(sm);
    const int tid = threadIdx.x, wid = tid >> 5, lane = tid & 31;
    const int z = blockIdx.z;
    const int b = z / (Hh * NB), h = (z / NB) % Hh, c = z % NB, hk = h >> 1;
    const float s = slope[h];
    const int m0 = blockIdx.y * 128, n0 = blockIdx.x * 128;
    const int wm = (wid & 1) * 64, wn = (wid >> 1) * 32;
    const int t4 = lane & 3, tq = lane >> 2;
    const int fr = tid >> 3, fc = tid & 7;

    const __nv_bfloat16* Ah = g_qh + (size_t)(b * Ls + c * BLK + m0) * HD + h * Dd;
    const __nv_bfloat16* Al = g_ql + (size_t)(b * Ls + c * BLK + m0) * HD + h * Dd;
    const __nv_bfloat16* Bh = g_kh + (size_t)(b * Ls + c * BLK + n0) * KD + hk * Dd;
    const __nv_bfloat16* Bl = g_kl + (size_t)(b * Ls + c * BLK + n0) * KD + hk * Dd;

    float acc[4][4][4] = {};

#define FILLSC(st, buf) do {                                                              \
    const uint32_t sb = sbase + (buf) * STAGE_B;                                          \
    const int k0 = (st) * 64;                                                             \
    fill_pair(sb + SA_H, sb + SA_L, Ah + k0, Al + k0, HD, fr, fc);                        \
    fill_pair(sb + SB_H, sb + SB_L, Bh + k0, Bl + k0, KD, fr, fc);                        \
} while (0)

    FILLSC(0, 0); CPCOMMIT();
    FILLSC(1, 1); CPCOMMIT();
    for (int st = 0; st < 4; st++) {
        CPWAIT1();
        __syncthreads();
        stage_mma(sbase + (st & 1) * STAGE_B, acc, wm, wn, tq, t4);
        __syncthreads();
        if (st + 2 < 4) FILLSC(st + 2, st & 1);
        CPCOMMIT();
    }
#undef FILLSC

    __nv_bfloat16* sh = g_sch + (size_t)z * 65536;
    __nv_bfloat16* sl = g_scl + (size_t)z * 65536;
#pragma unroll
    for (int mi = 0; mi < 4; mi++) {
        const int mA = m0 + wm + mi * 16 + tq, mB = mA + 8;
#pragma unroll
        for (int ni = 0; ni < 4; ni++) {
            const int cn = n0 + wn + ni * 8 + t4 * 2;
            float v0 = (mA >= cn)     ? acc[mi][ni][0] * expf(-s * (float)(mA - cn))     : 0.f;
            float v1 = (mA >= cn + 1) ? acc[mi][ni][1] * expf(-s * (float)(mA - cn - 1)) : 0.f;
            float v2 = (mB >= cn)     ? acc[mi][ni][2] * expf(-s * (float)(mB - cn))     : 0.f;
            float v3 = (mB >= cn + 1) ? acc[mi][ni][3] * expf(-s * (float)(mB - cn - 1)) : 0.f;
            uint32_t hh, ll;
            split2(v0, v1, hh, ll);
            *(uint32_t*)(sh + (size_t)mA * 256 + cn) = hh;
            *(uint32_t*)(sl + (size_t)mA * 256 + cn) = ll;
            split2(v2, v3, hh, ll);
            *(uint32_t*)(sh + (size_t)mB * 256 + cn) = hh;
            *(uint32_t*)(sl + (size_t)mB * 256 + cn) = ll;
        }
    }
}

__global__ __launch_bounds__(256, 1) void out_mma(const float* __restrict__ slope)
{
    extern __shared__ char sm[];
    const uint32_t sbase = smem_u32(sm);
    const int tid = threadIdx.x, wid = tid >> 5, lane = tid & 31;
    const int z = blockIdx.z;
    const int b = z / (Hh * NB), h = (z / NB) % Hh, c = z % NB, hk = h >> 1;
    const float s = slope[h];
    const int m0 = blockIdx.y * 128, n0 = blockIdx.x * 128;
    const int wm = (wid & 1) * 64, wn = (wid >> 1) * 32;
    const int t4 = lane & 3, tq = lane >> 2;
    const int fr = tid >> 3, fc = tid & 7;

    float acc[4][4][4] = {};

    {
        const __nv_bfloat16* Ah = g_qh + (size_t)(b * Ls + c * BLK + m0) * HD + h * Dd;
        const __nv_bfloat16* Al = g_ql + (size_t)(b * Ls + c * BLK + m0) * HD + h * Dd;
        const __nv_bfloat16* Bh = g_kvTh + (size_t)z * 65536 + (size_t)n0 * 256;
        const __nv_bfloat16* Bl = g_kvTl + (size_t)z * 65536 + (size_t)n0 * 256;
#define FILLO1(st, buf) do {                                                              \
    const uint32_t sb = sbase + (buf) * STAGE_B;                                          \
    const int k0 = (st) * 64;                                                             \
    fill_pair(sb + SA_H, sb + SA_L, Ah + k0, Al + k0, HD, fr, fc);                        \
    fill_pair(sb + SB_H, sb + SB_L, Bh + k0, Bl + k0, 256, fr, fc);                       \
} while (0)
        FILLO1(0, 0); CPCOMMIT();
        FILLO1(1, 1); CPCOMMIT();
        for (int st = 0; st < 4; st++) {
            CPWAIT1();
            __syncthreads();
            stage_mma(sbase + (st & 1) * STAGE_B, acc, wm, wn, tq, t4);
            __syncthreads();
            if (st + 2 < 4) FILLO1(st + 2, st & 1);
            CPCOMMIT();
        }
#undef FILLO1
    }

#pragma unroll
    for (int mi = 0; mi < 4; mi++) {
        const int mA = m0 + wm + mi * 16 + tq;
        const float qd0 = expf(-s * (float)(mA + 1));
        const float qd1 = expf(-s * (float)(mA + 9));
#pragma unroll
        for (int ni = 0; ni < 4; ni++) {
            acc[mi][ni][0] *= qd0;
            acc[mi][ni][1] *= qd0;
            acc[mi][ni][2] *= qd1;
            acc[mi][ni][3] *= qd1;
        }
    }

    {
        const __nv_bfloat16* Ah = g_sch + (size_t)z * 65536 + (size_t)m0 * 256;
        const __nv_bfloat16* Al = g_scl + (size_t)z * 65536 + (size_t)m0 * 256;
        const __nv_bfloat16* Bh = g_vTh + ((size_t)(b * 8 + hk) * Dd + n0) * Ls + c * BLK;
        const __nv_bfloat16* Bl = g_vTl + ((size_t)(b * 8 + hk) * Dd + n0) * Ls + c * BLK;
#define FILLO2(st, buf) do {                                                              \
    const uint32_t sb = sbase + (buf) * STAGE_B;                                          \
    const int k0 = (st) * 64;                                                             \
    fill_pair(sb + SA_H, sb + SA_L, Ah + k0, Al + k0, 256, fr, fc);                       \
    fill_pair(sb + SB_H, sb + SB_L, Bh + k0, Bl + k0, Ls, fr, fc);                        \
} while (0)
        FILLO2(0, 0); CPCOMMIT();
        FILLO2(1, 1); CPCOMMIT();
        for (int st = 0; st < 4; st++) {
            CPWAIT1();
            __syncthreads();
            stage_mma(sbase + (st & 1) * STAGE_B, acc, wm, wn, tq, t4);
            __syncthreads();
            if (st + 2 < 4) FILLO2(st + 2, st & 1);
            CPCOMMIT();
        }
#undef FILLO2
    }

    float* op = g_o + (size_t)(b * Ls + c * BLK) * HD + h * Dd;
#pragma unroll
    for (int mi = 0; mi < 4; mi++) {
        const int mA = m0 + wm + mi * 16 + tq, mB = mA + 8;
#pragma unroll
        for (int ni = 0; ni < 4; ni++) {
            const int cn = n0 + wn + ni * 8 + t4 * 2;
            *(float2*)(op + (size_t)mA * HD + cn) = make_float2(acc[mi][ni][0], acc[mi][ni][1]);
            *(float2*)(op + (size_t)mB * HD + cn) = make_float2(acc[mi][ni][2], acc[mi][ni][3]);
        }
    }
}

// ---------------- SimpleRMSNorm + bf16 hi/lo split output ----------------
__global__ __launch_bounds__(256) void rmsnorm_split_kernel()
{
    const int row = blockIdx.x;
    const float* p = g_o + (size_t)row * HD;
    __nv_bfloat16* oh = g_oh + (size_t)row * HD;
    __nv_bfloat16* ol = g_ol + (size_t)row * HD;
    const int tid = threadIdx.x;
    float ss = 0.f;
    for (int i = tid; i < HD; i += 256) {
        float v = p[i];
        ss += v * v;
    }
#pragma unroll
    for (int off = 16; off > 0; off >>= 1) ss += __shfl_xor_sync(0xffffffffu, ss, off);
    __shared__ float red[8];
    __shared__ float scale_s;
    if ((tid & 31) == 0) red[tid >> 5] = ss;
    __syncthreads();
    if (tid == 0) {
        float tot = 0.f;
#pragma unroll
        for (int w = 0; w < 8; w++) tot += red[w];
        scale_s = rsqrtf(tot / (float)HD + 1e-6f);
    }
    __syncthreads();
    const float sc = scale_s;
    for (int i = tid * 2; i < HD; i += 512) {
        float v0 = p[i] * sc, v1 = p[i + 1] * sc;
        uint32_t h, l;
        split2(v0, v1, h, l);
        *(uint32_t*)(oh + i) = h;
        *(uint32_t*)(ol + i) = l;
    }
}

// ---------------- launcher ----------------
extern "C" void kernel_launch(void* const* d_in, const int* in_sizes, int n_in,
                              void* d_out, int out_size)
{
    const float* x     = (const float*)d_in[0];
    const float* Wq    = (const float*)d_in[1];
    const float* Wk    = (const float*)d_in[2];
    const float* Wv    = (const float*)d_in[3];
    const float* Wo    = (const float*)d_in[4];
    const float* cqw   = (const float*)d_in[5];
    const float* cqb   = (const float*)d_in[6];
    const float* ckw   = (const float*)d_in[7];
    const float* ckb   = (const float*)d_in[8];
    const float* slope = (const float*)d_in[9];
    float* out = (float*)d_out;

    static cudaStream_t s2 = nullptr;
    static cudaEvent_t evF, ev1, ev2, ev3, ev4;
    if (!s2) {
        cudaStreamCreateWithFlags(&s2, cudaStreamNonBlocking);
        cudaEventCreateWithFlags(&evF, cudaEventDisableTiming);
        cudaEventCreateWithFlags(&ev1, cudaEventDisableTiming);
        cudaEventCreateWithFlags(&ev2, cudaEventDisableTiming);
        cudaEventCreateWithFlags(&ev3, cudaEventDisableTiming);
        cudaEventCreateWithFlags(&ev4, cudaEventDisableTiming);
    }

    float *qkvpre, *kf;
    __nv_bfloat16 *xh, *xl, *wqkvh, *wqkvl, *woh, *wol, *oh, *ol;
    cudaGetSymbolAddress((void**)&qkvpre, g_qkvpre);
    cudaGetSymbolAddress((void**)&kf,     g_kf);
    cudaGetSymbolAddress((void**)&xh,     g_xh);
    cudaGetSymbolAddress((void**)&xl,     g_xl);
    cudaGetSymbolAddress((void**)&wqkvh,  g_wqkvh);
    cudaGetSymbolAddress((void**)&wqkvl,  g_wqkvl);
    cudaGetSymbolAddress((void**)&woh,    g_woh);
    cudaGetSymbolAddress((void**)&wol,    g_wol);
    cudaGetSymbolAddress((void**)&oh,     g_oh);
    cudaGetSymbolAddress((void**)&ol,     g_ol);
    __nv_bfloat16 *qh, *ql, *kh, *kl, *vth, *vtl;
    cudaGetSymbolAddress((void**)&qh,  g_qh);
    cudaGetSymbolAddress((void**)&ql,  g_ql);
    cudaGetSymbolAddress((void**)&kh,  g_kh);
    cudaGetSymbolAddress((void**)&kl,  g_kl);
    cudaGetSymbolAddress((void**)&vth, g_vTh);
    cudaGetSymbolAddress((void**)&vtl, g_vTl);
    float* kT;
    cudaGetSymbolAddress((void**)&kT, g_kT);

    cudaFuncSetAttribute(hgemm2,    cudaFuncAttributeMaxDynamicSharedMemorySize, G2_SMEM);
    cudaFuncSetAttribute(kvloc_mma, cudaFuncAttributeMaxDynamicSharedMemorySize, HG_SMEM);
    cudaFuncSetAttribute(sc_mma,    cudaFuncAttributeMaxDynamicSharedMemorySize, HG_SMEM);
    cudaFuncSetAttribute(out_mma,   cudaFuncAttributeMaxDynamicSharedMemorySize, HG_SMEM);

    const int M = Bb * Ls;   // 4096

    // ---- fork: weight preparation on side stream ----
    cudaEventRecord(evF, 0);
    cudaStreamWaitEvent(s2, evF, 0);
    tsplit<<<dim3(HD / 32, HIDd / 32), 256, 0, s2>>>(Wq, wqkvh, wqkvl, HIDd, HD);
    tsplit<<<dim3(KD / 32, HIDd / 32), 256, 0, s2>>>(Wk, wqkvh + (size_t)HD * HIDd,
                                                     wqkvl + (size_t)HD * HIDd, HIDd, KD);
    tsplit<<<dim3(KD / 32, HIDd / 32), 256, 0, s2>>>(Wv, wqkvh + (size_t)(HD + KD) * HIDd,
                                                     wqkvl + (size_t)(HD + KD) * HIDd, HIDd, KD);
    cudaEventRecord(ev1, s2);
    tsplit<<<dim3(HIDd / 32, HD / 32), 256, 0, s2>>>(Wo, woh, wol, HD, HIDd);
    cudaEventRecord(ev2, s2);

    // ---- main stream ----
    convsplit<<<(M * HIDd / 4 + 255) / 256, 256>>>(x, xh, xl, M * HIDd / 4);
    cudaStreamWaitEvent(0, ev1, 0);

    // fused QKV projection
    hgemm2<<<dim3(NQKV / 256, M / 128), 256, G2_SMEM>>>(xh, xl, wqkvh, wqkvl, qkvpre, M, NQKV, HIDd);

    // conv + silu (q from cols [0,4096), k from cols [4096,6144))
    conv_silu_split<<<(M * HD / 2 + 255) / 256, 256>>>(qkvpre, NQKV, cqw, cqb, qh, ql, nullptr, HD, M * HD / 2);
    conv_silu_split<<<(M * KD / 2 + 255) / 256, 256>>>(qkvpre + HD, NQKV, ckw, ckb, kh, kl, kf, KD, M * KD / 2);
    cudaEventRecord(ev3, 0);

    // sc_mma overlaps with transposes + kvloc + prefix
    cudaStreamWaitEvent(s2, ev3, 0);
    sc_mma<<<dim3(2, 2, Bb * Hh * NB), 256, HG_SMEM, s2>>>(slope);
    cudaEventRecord(ev4, s2);

    trans_split<<<dim3(Ls / 32, Dd / 32, 16), 256>>>(qkvpre, NQKV, HD + KD, vth, vtl);
    trans_f32<<<dim3(Ls / 32, Dd / 32, 16), 256>>>(kf, kT);
    kvloc_mma<<<dim3(2, 2, Bb * Hh * NB), 256, HG_SMEM>>>(slope);
    kvprefix_split<<<(Bb * Hh * 32768) / 256, 256>>>(slope);

    cudaStreamWaitEvent(0, ev4, 0);
    out_mma<<<dim3(2, 2, Bb * Hh * NB), 256, HG_SMEM>>>(slope);

    // norm + split + output projection
    rmsnorm_split_kernel<<<M, 256>>>();
    cudaStreamWaitEvent(0, ev2, 0);
    hgemm2<<<dim3(HIDd / 256, M / 128), 256, G2_SMEM>>>(oh, ol, woh, wol, out, M, HIDd, HD);
}

// round 7
// speedup vs baseline: 3.3608x; 1.0070x over previous
#include <cuda_runtime.h>
#include <cuda_bf16.h>
#include <cstdint>

#define Bb   2
#define Ls   2048
#define Hh   16
#define Dd   256
#define HD   4096   // H*D
#define KD   2048   // HKV*D
#define HIDd 2048
#define NB   8
#define BLK  256
#define NQKV 8192   // HD + KD + KD

// ---------------- scratch (static device memory; no allocs) ----------------
static __device__ __align__(128) float g_qkvpre[Bb * Ls * NQKV];
static __device__ __align__(128) float g_kf  [Bb * Ls * KD];
static __device__ __align__(128) float g_kv  [Bb * Hh * NB * Dd * Dd];
static __device__ __align__(128) float g_o   [Bb * Ls * HD];
static __device__ __align__(128) float g_kT  [16 * Dd * Ls];

static __device__ __align__(128) __nv_bfloat16 g_xh   [Bb * Ls * HIDd];
static __device__ __align__(128) __nv_bfloat16 g_xl   [Bb * Ls * HIDd];
static __device__ __align__(128) __nv_bfloat16 g_wqkvh[NQKV * HIDd];
static __device__ __align__(128) __nv_bfloat16 g_wqkvl[NQKV * HIDd];
static __device__ __align__(128) __nv_bfloat16 g_woh  [HIDd * HD];
static __device__ __align__(128) __nv_bfloat16 g_wol  [HIDd * HD];
static __device__ __align__(128) __nv_bfloat16 g_oh   [Bb * Ls * HD];
static __device__ __align__(128) __nv_bfloat16 g_ol   [Bb * Ls * HD];
static __device__ __align__(128) __nv_bfloat16 g_qh   [Bb * Ls * HD];
static __device__ __align__(128) __nv_bfloat16 g_ql   [Bb * Ls * HD];
static __device__ __align__(128) __nv_bfloat16 g_kh   [Bb * Ls * KD];
static __device__ __align__(128) __nv_bfloat16 g_kl   [Bb * Ls * KD];
static __device__ __align__(128) __nv_bfloat16 g_vTh  [16 * Dd * Ls];
static __device__ __align__(128) __nv_bfloat16 g_vTl  [16 * Dd * Ls];
static __device__ __align__(128) __nv_bfloat16 g_kvTh [Bb * Hh * NB * Dd * Dd];
static __device__ __align__(128) __nv_bfloat16 g_kvTl [Bb * Hh * NB * Dd * Dd];
static __device__ __align__(128) __nv_bfloat16 g_sch  [Bb * Hh * NB * BLK * BLK];
static __device__ __align__(128) __nv_bfloat16 g_scl  [Bb * Hh * NB * BLK * BLK];

// =======================================================================
// helpers
// =======================================================================
__device__ __forceinline__ uint32_t smem_u32(const void* p) {
    uint32_t a;
    asm("{ .reg .u64 t; cvta.to.shared.u64 t, %1; cvt.u32.u64 %0, t; }" : "=r"(a) : "l"(p));
    return a;
}
__device__ __forceinline__ void split2(float x0, float x1, uint32_t& hi, uint32_t& lo) {
    __nv_bfloat16 h0 = __float2bfloat16_rn(x0);
    __nv_bfloat16 h1 = __float2bfloat16_rn(x1);
    float r0 = x0 - __bfloat162float(h0);
    float r1 = x1 - __bfloat162float(h1);
    __nv_bfloat162 hp; hp.x = h0; hp.y = h1;
    __nv_bfloat162 lp = __floats2bfloat162_rn(r0, r1);
    hi = *reinterpret_cast<uint32_t*>(&hp);
    lo = *reinterpret_cast<uint32_t*>(&lp);
}
#define CPA16(dst, src) asm volatile("cp.async.cg.shared.global [%0], [%1], 16;" :: "r"(dst), "l"(src))
#define CPCOMMIT()      asm volatile("cp.async.commit_group;" ::: "memory")
#define CPWAIT1()       asm volatile("cp.async.wait_group 1;" ::: "memory")
__device__ __forceinline__ void ldsm4(uint32_t a, uint32_t* r) {
    asm volatile("ldmatrix.sync.aligned.m8n8.x4.shared.b16 {%0,%1,%2,%3}, [%4];"
                 : "=r"(r[0]), "=r"(r[1]), "=r"(r[2]), "=r"(r[3]) : "r"(a));
}
__device__ __forceinline__ void mma16816(float* d, const uint32_t* a, const uint32_t* b) {
    asm volatile("mma.sync.aligned.m16n8k16.row.col.f32.bf16.bf16.f32 "
                 "{%0,%1,%2,%3}, {%4,%5,%6,%7}, {%8,%9}, {%0,%1,%2,%3};"
                 : "+f"(d[0]), "+f"(d[1]), "+f"(d[2]), "+f"(d[3])
                 : "r"(a[0]), "r"(a[1]), "r"(a[2]), "r"(a[3]), "r"(b[0]), "r"(b[1]));
}

// ---------- 128x128-tile layout (attention kernels) ----------
#define SA_H 0
#define SA_L 16384
#define SB_H 32768
#define SB_L 49152
#define STAGE_B 65536
#define HG_SMEM (2 * STAGE_B)

// one BK=64 stage: ldmatrix-based fragment loads, 3-term split MMA
__device__ __forceinline__ void stage_mma(uint32_t sb, float acc[4][4][4],
                                          int wm, int wn, int lane)
{
    const int rA = lane & 15, kA = lane >> 4;
    const int rB = (lane & 7) | ((lane & 16) >> 1), kB = (lane >> 3) & 1;
    const int e = lane & 7;
    const uint32_t baseA = sb + (uint32_t)((wm + rA) * 128);
    const uint32_t baseB = sb + (uint32_t)((wn + rB) * 128);
#pragma unroll
    for (int kk = 0; kk < 4; kk++) {
        const uint32_t cA = (uint32_t)(((2 * kk + kA) ^ e) << 4);
        const uint32_t cB = (uint32_t)(((2 * kk + kB) ^ e) << 4);
        uint32_t ah[4][4], al[4][4], bh[2][4], bl[2][4];
#pragma unroll
        for (int mi = 0; mi < 4; mi++) {
            ldsm4(baseA + SA_H + mi * 2048 + cA, ah[mi]);
            ldsm4(baseA + SA_L + mi * 2048 + cA, al[mi]);
        }
#pragma unroll
        for (int nj = 0; nj < 2; nj++) {
            ldsm4(baseB + SB_H + nj * 2048 + cB, bh[nj]);
            ldsm4(baseB + SB_L + nj * 2048 + cB, bl[nj]);
        }
#pragma unroll
        for (int mi = 0; mi < 4; mi++)
#pragma unroll
            for (int ni = 0; ni < 4; ni++) {
                const uint32_t* bph = &bh[ni >> 1][(ni & 1) * 2];
                const uint32_t* bpl = &bl[ni >> 1][(ni & 1) * 2];
                mma16816(acc[mi][ni], ah[mi], bph);
                mma16816(acc[mi][ni], al[mi], bph);
                mma16816(acc[mi][ni], ah[mi], bpl);
            }
    }
}

__device__ __forceinline__ void fill_pair(uint32_t sb_h, uint32_t sb_l,
                                          const __nv_bfloat16* gh, const __nv_bfloat16* gl,
                                          size_t stride, int fr, int fc)
{
#pragma unroll
    for (int i = 0; i < 4; i++) {
        int r = fr + 32 * i;
        uint32_t doff = (uint32_t)(r * 128 + ((fc ^ (r & 7)) << 4));
        size_t so = (size_t)r * stride + fc * 8;
        CPA16(sb_h + doff, gh + so);
        CPA16(sb_l + doff, gl + so);
    }
}

__device__ __forceinline__ void fill_f32_decay(char* smh, char* sml,
                                               const float* g, size_t stride,
                                               int fr, int fc, float kd0, float ek)
{
    float kd[8];
    kd[0] = kd0;
#pragma unroll
    for (int j = 1; j < 8; j++) kd[j] = kd[j - 1] * ek;
#pragma unroll
    for (int i = 0; i < 4; i++) {
        int r = fr + 32 * i;
        uint32_t doff = (uint32_t)(r * 128 + ((fc ^ (r & 7)) << 4));
        const float* sp = g + (size_t)r * stride + fc * 8;
        float4 u = *(const float4*)sp;
        float4 w = *(const float4*)(sp + 4);
        uint4 hi, lo;
        split2(u.x * kd[0], u.y * kd[1], hi.x, lo.x);
        split2(u.z * kd[2], u.w * kd[3], hi.y, lo.y);
        split2(w.x * kd[4], w.y * kd[5], hi.z, lo.z);
        split2(w.z * kd[6], w.w * kd[7], hi.w, lo.w);
        *(uint4*)(smh + doff) = hi;
        *(uint4*)(sml + doff) = lo;
    }
}

// =======================================================================
// hgemm2: 128(M) x 256(N) tile, BK=64, 2-stage
// =======================================================================
#define G2_SA_H 0
#define G2_SA_L 16384
#define G2_SB_H 32768
#define G2_SB_L 65536
#define G2_STAGE 98304
#define G2_SMEM (2 * G2_STAGE)

__global__ __launch_bounds__(256, 1) void hgemm2(const __nv_bfloat16* __restrict__ Ah,
                                                 const __nv_bfloat16* __restrict__ Al,
                                                 const __nv_bfloat16* __restrict__ Bh,
                                                 const __nv_bfloat16* __restrict__ Bl,
                                                 float* __restrict__ C,
                                                 int M, int N, int K)
{
    extern __shared__ char sm[];
    const uint32_t sbase = smem_u32(sm);
    const int tid = threadIdx.x, wid = tid >> 5, lane = tid & 31;
    const int m0 = blockIdx.y * 128, n0 = blockIdx.x * 256;
    const int wm = (wid & 1) * 64, wn = (wid >> 1) * 64;
    const int t4 = lane & 3, tq = lane >> 2;
    const int fr = tid >> 3, fc = tid & 7;

    const int rA = lane & 15, kA = lane >> 4;
    const int rB = (lane & 7) | ((lane & 16) >> 1), kB = (lane >> 3) & 1;
    const int e = lane & 7;

    float acc[4][8][4];
#pragma unroll
    for (int a = 0; a < 4; a++)
#pragma unroll
        for (int b = 0; b < 8; b++)
#pragma unroll
            for (int c = 0; c < 4; c++) acc[a][b][c] = 0.f;

#define FILL2(s, buf) do {                                                                \
    const uint32_t sb = sbase + (buf) * G2_STAGE;                                         \
    const int k0 = (s) * 64;                                                              \
    _Pragma("unroll")                                                                     \
    for (int i = 0; i < 4; i++) {                                                         \
        int r = fr + 32 * i;                                                              \
        uint32_t doff = (uint32_t)(r * 128 + ((fc ^ (r & 7)) << 4));                      \
        size_t so = (size_t)(m0 + r) * K + k0 + fc * 8;                                   \
        CPA16(sb + G2_SA_H + doff, Ah + so);                                              \
        CPA16(sb + G2_SA_L + doff, Al + so);                                              \
    }                                                                                     \
    _Pragma("unroll")                                                                     \
    for (int i = 0; i < 8; i++) {                                                         \
        int r = fr + 32 * i;                                                              \
        uint32_t doff = (uint32_t)(r * 128 + ((fc ^ (r & 7)) << 4));                      \
        size_t so = (size_t)(n0 + r) * K + k0 + fc * 8;                                   \
        CPA16(sb + G2_SB_H + doff, Bh + so);                                              \
        CPA16(sb + G2_SB_L + doff, Bl + so);                                              \
    }                                                                                     \
} while (0)

    const int S = K / 64;
    FILL2(0, 0); CPCOMMIT();
    FILL2(1, 1); CPCOMMIT();

    for (int s = 0; s < S; s++) {
        CPWAIT1();
        __syncthreads();
        const uint32_t sb = sbase + (s & 1) * G2_STAGE;
        const uint32_t baseA = sb + (uint32_t)((wm + rA) * 128);
        const uint32_t baseB = sb + (uint32_t)((wn + rB) * 128);
#pragma unroll
        for (int kk = 0; kk < 4; kk++) {
            const uint32_t cA = (uint32_t)(((2 * kk + kA) ^ e) << 4);
            const uint32_t cB = (uint32_t)(((2 * kk + kB) ^ e) << 4);
            uint32_t ah[4][4], al[4][4], bh[4][4], bl[4][4];
#pragma unroll
            for (int mi = 0; mi < 4; mi++) {
                ldsm4(baseA + G2_SA_H + mi * 2048 + cA, ah[mi]);
                ldsm4(baseA + G2_SA_L + mi * 2048 + cA, al[mi]);
            }
#pragma unroll
            for (int nj = 0; nj < 4; nj++) {
                ldsm4(baseB + G2_SB_H + nj * 2048 + cB, bh[nj]);
                ldsm4(baseB + G2_SB_L + nj * 2048 + cB, bl[nj]);
            }
#pragma unroll
            for (int mi = 0; mi < 4; mi++)
#pragma unroll
                for (int ni = 0; ni < 8; ni++) {
                    const uint32_t* bph = &bh[ni >> 1][(ni & 1) * 2];
                    const uint32_t* bpl = &bl[ni >> 1][(ni & 1) * 2];
                    mma16816(acc[mi][ni], ah[mi], bph);
                    mma16816(acc[mi][ni], al[mi], bph);
                    mma16816(acc[mi][ni], ah[mi], bpl);
                }
        }
        __syncthreads();
        if (s + 2 < S) FILL2(s + 2, s & 1);
        CPCOMMIT();
    }
#undef FILL2

#pragma unroll
    for (int mi = 0; mi < 4; mi++) {
        const int m = m0 + wm + mi * 16 + tq;
#pragma unroll
        for (int ni = 0; ni < 8; ni++) {
            const int n = n0 + wn + ni * 8 + t4 * 2;
            *(float2*)(C + (size_t)m * N + n)       = make_float2(acc[mi][ni][0], acc[mi][ni][1]);
            *(float2*)(C + (size_t)(m + 8) * N + n) = make_float2(acc[mi][ni][2], acc[mi][ni][3]);
        }
    }
}

// =======================================================================
// convert kernels
// =======================================================================
__global__ __launch_bounds__(256) void convsplit(const float* __restrict__ in,
                                                 __nv_bfloat16* __restrict__ hi,
                                                 __nv_bfloat16* __restrict__ lo, int n4)
{
    int i = blockIdx.x * 256 + threadIdx.x;
    if (i >= n4) return;
    float4 v = ((const float4*)in)[i];
    uint2 h, l;
    split2(v.x, v.y, h.x, l.x);
    split2(v.z, v.w, h.y, l.y);
    ((uint2*)hi)[i] = h;
    ((uint2*)lo)[i] = l;
}

__global__ __launch_bounds__(256) void tsplit(const float* __restrict__ W,
                                              __nv_bfloat16* __restrict__ th,
                                              __nv_bfloat16* __restrict__ tl,
                                              int Kd, int Nd)
{
    __shared__ float t[32][33];
    const int bxn = blockIdx.x * 32;
    const int byk = blockIdx.y * 32;
    const int x = threadIdx.x & 31, y = threadIdx.x >> 5;
#pragma unroll
    for (int j = 0; j < 4; j++)
        t[y + 8 * j][x] = W[(size_t)(byk + y + 8 * j) * Nd + bxn + x];
    __syncthreads();
    const int n = bxn + x;
    float v0 = t[y * 4 + 0][x];
    float v1 = t[y * 4 + 1][x];
    float v2 = t[y * 4 + 2][x];
    float v3 = t[y * 4 + 3][x];
    uint2 h, l;
    split2(v0, v1, h.x, l.x);
    split2(v2, v3, h.y, l.y);
    size_t off = ((size_t)n * Kd + byk + y * 4) >> 2;
    ((uint2*)th)[off] = h;
    ((uint2*)tl)[off] = l;
}

__global__ __launch_bounds__(256) void trans_f32(const float* __restrict__ in,
                                                 float* __restrict__ out)
{
    __shared__ float t[32][33];
    const int bk = blockIdx.z;
    const int b = bk >> 3, hk = bk & 7;
    const int l0 = blockIdx.x * 32, d0 = blockIdx.y * 32;
    const int x = threadIdx.x & 31, y = threadIdx.x >> 5;
#pragma unroll
    for (int j = 0; j < 4; j++)
        t[y + 8 * j][x] = in[(size_t)(b * Ls + l0 + y + 8 * j) * KD + hk * Dd + d0 + x];
    __syncthreads();
#pragma unroll
    for (int j = 0; j < 4; j++) {
        int d = d0 + y + 8 * j;
        out[((size_t)bk * Dd + d) * Ls + l0 + x] = t[x][y + 8 * j];
    }
}

__global__ __launch_bounds__(256) void trans_split(const float* __restrict__ in,
                                                   int instride, int colbase,
                                                   __nv_bfloat16* __restrict__ oth,
                                                   __nv_bfloat16* __restrict__ otl)
{
    __shared__ float t[32][33];
    const int bk = blockIdx.z;
    const int b = bk >> 3, hk = bk & 7;
    const int l0 = blockIdx.x * 32, d0 = blockIdx.y * 32;
    const int x = threadIdx.x & 31, y = threadIdx.x >> 5;
#pragma unroll
    for (int j = 0; j < 4; j++)
        t[y + 8 * j][x] = in[(size_t)(b * Ls + l0 + y + 8 * j) * instride + colbase + hk * Dd + d0 + x];
    __syncthreads();
    const int x2 = threadIdx.x & 15, yy = threadIdx.x >> 4;
#pragma unroll
    for (int j = 0; j < 2; j++) {
        int d = d0 + yy + 16 * j;
        float v0 = t[x2 * 2][yy + 16 * j];
        float v1 = t[x2 * 2 + 1][yy + 16 * j];
        uint32_t h, l;
        split2(v0, v1, h, l);
        size_t off = (((size_t)bk * Dd + d) * Ls + l0 + x2 * 2) >> 1;
        ((uint32_t*)oth)[off] = h;
        ((uint32_t*)otl)[off] = l;
    }
}

__global__ __launch_bounds__(256) void conv_silu_split(const float* __restrict__ in,
                                                       int instride,
                                                       const float* __restrict__ w,
                                                       const float* __restrict__ bias,
                                                       __nv_bfloat16* __restrict__ oh,
                                                       __nv_bfloat16* __restrict__ ol,
                                                       float* __restrict__ of32,
                                                       int C, int npairs)
{
    int p = blockIdx.x * 256 + threadIdx.x;
    if (p >= npairs) return;
    const int Ch = C >> 1;
    int row = p / Ch;
    int c = (p - row * Ch) * 2;
    int l = row & (Ls - 1);
    const float* ip = in + (size_t)row * instride + c;
    float a0 = bias[c], a1 = bias[c + 1];
#pragma unroll
    for (int t = 0; t < 4; t++) {
        int ls = l + t - 3;
        if (ls >= 0) {
            a0 += w[c * 4 + t]       * ip[(ptrdiff_t)(t - 3) * instride];
            a1 += w[(c + 1) * 4 + t] * ip[(ptrdiff_t)(t - 3) * instride + 1];
        }
    }
    a0 = a0 / (1.f + expf(-a0));
    a1 = a1 / (1.f + expf(-a1));
    size_t oidx = (size_t)row * C + c;
    if (of32) { of32[oidx] = a0; of32[oidx + 1] = a1; }
    uint32_t h, lo;
    split2(a0, a1, h, lo);
    ((uint32_t*)oh)[oidx >> 1] = h;
    ((uint32_t*)ol)[oidx >> 1] = lo;
}

// =======================================================================
// attention MMA kernels
// =======================================================================
__global__ __launch_bounds__(256, 1) void kvloc_mma(const float* __restrict__ slope)
{
    extern __shared__ char sm[];
    const uint32_t sbase = smem_u32(sm);
    const int tid = threadIdx.x, wid = tid >> 5, lane = tid & 31;
    const int z = blockIdx.z;
    const int b = z / (Hh * NB), h = (z / NB) % Hh, c = z % NB, hk = h >> 1;
    const float s = slope[h];
    const int m0 = blockIdx.y * 128, n0 = blockIdx.x * 128;
    const int wm = (wid & 1) * 64, wn = (wid >> 1) * 32;
    const int t4 = lane & 3, tq = lane >> 2;
    const int fr = tid >> 3, fc = tid & 7;

    const __nv_bfloat16* Avh = g_vTh + ((size_t)(b * 8 + hk) * Dd + m0) * Ls + c * BLK;
    const __nv_bfloat16* Avl = g_vTl + ((size_t)(b * 8 + hk) * Dd + m0) * Ls + c * BLK;
    const float* BkT = g_kT + ((size_t)(b * 8 + hk) * Dd + n0) * Ls + c * BLK;
    const float ek = expf(s);

    float acc[4][4][4] = {};

#define FILLKV(st, buf) do {                                                              \
    const uint32_t sb = sbase + (buf) * STAGE_B;                                          \
    char* smb = sm + (buf) * STAGE_B;                                                     \
    const int k0 = (st) * 64;                                                             \
    fill_pair(sb + SA_H, sb + SA_L, Avh + k0, Avl + k0, Ls, fr, fc);                      \
    float kd0 = expf(-s * (float)(255 - (k0 + fc * 8)));                                  \
    fill_f32_decay(smb + SB_H, smb + SB_L, BkT + k0, Ls, fr, fc, kd0, ek);                \
} while (0)

    FILLKV(0, 0); CPCOMMIT();
    FILLKV(1, 1); CPCOMMIT();
    for (int st = 0; st < 4; st++) {
        CPWAIT1();
        __syncthreads();
        stage_mma(sbase + (st & 1) * STAGE_B, acc, wm, wn, lane);
        __syncthreads();
        if (st + 2 < 4) FILLKV(st + 2, st & 1);
        CPCOMMIT();
    }
#undef FILLKV

    float* op = g_kv + (size_t)z * 65536;
#pragma unroll
    for (int mi = 0; mi < 4; mi++) {
        const int mA = m0 + wm + mi * 16 + tq, mB = mA + 8;
#pragma unroll
        for (int ni = 0; ni < 4; ni++) {
            const int cn = n0 + wn + ni * 8 + t4 * 2;
            *(float2*)(op + (size_t)mA * 256 + cn) = make_float2(acc[mi][ni][0], acc[mi][ni][1]);
            *(float2*)(op + (size_t)mB * 256 + cn) = make_float2(acc[mi][ni][2], acc[mi][ni][3]);
        }
    }
}

__global__ __launch_bounds__(256) void kvprefix_split(const float* __restrict__ slope)
{
    const int pidx = blockIdx.x * 256 + threadIdx.x;
    const int bh = pidx >> 15;
    const int off = (pidx & 32767) * 2;
    const int h = bh % Hh;
    const float bdec = expf(-slope[h] * (float)BLK);
    const float* p = g_kv + (size_t)bh * NB * 65536 + off;
    __nv_bfloat16* oh = g_kvTh + (size_t)bh * NB * 65536 + off;
    __nv_bfloat16* ol = g_kvTl + (size_t)bh * NB * 65536 + off;
    float a0 = 0.f, a1 = 0.f;
#pragma unroll
    for (int c = 0; c < NB; c++) {
        float2 loc = *(const float2*)(p + (size_t)c * 65536);
        uint32_t hh, ll;
        split2(a0, a1, hh, ll);
        *(uint32_t*)(oh + (size_t)c * 65536) = hh;
        *(uint32_t*)(ol + (size_t)c * 65536) = ll;
        a0 = a0 * bdec + loc.x;
        a1 = a1 * bdec + loc.y;
    }
}

__global__ __launch_bounds__(256, 1) void sc_mma(const float* __restrict__ slope)
{
    extern __shared__ char sm[];
    const uint32_t sbase = smem_u32(sm);
    const int tid = threadIdx.x, wid = tid >> 5, lane = tid & 31;
    const int z = blockIdx.z;
    const int b = z / (Hh * NB), h = (z / NB) % Hh, c = z % NB, hk = h >> 1;
    const float s = slope[h];
    const int m0 = blockIdx.y * 128, n0 = blockIdx.x * 128;
    const int wm = (wid & 1) * 64, wn = (wid >> 1) * 32;
    const int t4 = lane & 3, tq = lane >> 2;
    const int fr = tid >> 3, fc = tid & 7;

    const __nv_bfloat16* Ah = g_qh + (size_t)(b * Ls + c * BLK + m0) * HD + h * Dd;
    const __nv_bfloat16* Al = g_ql + (size_t)(b * Ls + c * BLK + m0) * HD + h * Dd;
    const __nv_bfloat16* Bh = g_kh + (size_t)(b * Ls + c * BLK + n0) * KD + hk * Dd;
    const __nv_bfloat16* Bl = g_kl + (size_t)(b * Ls + c * BLK + n0) * KD + hk * Dd;

    float acc[4][4][4] = {};

#define FILLSC(st, buf) do {                                                              \
    const uint32_t sb = sbase + (buf) * STAGE_B;                                          \
    const int k0 = (st) * 64;                                                             \
    fill_pair(sb + SA_H, sb + SA_L, Ah + k0, Al + k0, HD, fr, fc);                        \
    fill_pair(sb + SB_H, sb + SB_L, Bh + k0, Bl + k0, KD, fr, fc);                        \
} while (0)

    FILLSC(0, 0); CPCOMMIT();
    FILLSC(1, 1); CPCOMMIT();
    for (int st = 0; st < 4; st++) {
        CPWAIT1();
        __syncthreads();
        stage_mma(sbase + (st & 1) * STAGE_B, acc, wm, wn, lane);
        __syncthreads();
        if (st + 2 < 4) FILLSC(st + 2, st & 1);
        CPCOMMIT();
    }
#undef FILLSC

    __nv_bfloat16* sh = g_sch + (size_t)z * 65536;
    __nv_bfloat16* sl = g_scl + (size_t)z * 65536;
#pragma unroll
    for (int mi = 0; mi < 4; mi++) {
        const int mA = m0 + wm + mi * 16 + tq, mB = mA + 8;
#pragma unroll
        for (int ni = 0; ni < 4; ni++) {
            const int cn = n0 + wn + ni * 8 + t4 * 2;
            float v0 = (mA >= cn)     ? acc[mi][ni][0] * expf(-s * (float)(mA - cn))     : 0.f;
            float v1 = (mA >= cn + 1) ? acc[mi][ni][1] * expf(-s * (float)(mA - cn - 1)) : 0.f;
            float v2 = (mB >= cn)     ? acc[mi][ni][2] * expf(-s * (float)(mB - cn))     : 0.f;
            float v3 = (mB >= cn + 1) ? acc[mi][ni][3] * expf(-s * (float)(mB - cn - 1)) : 0.f;
            uint32_t hh, ll;
            split2(v0, v1, hh, ll);
            *(uint32_t*)(sh + (size_t)mA * 256 + cn) = hh;
            *(uint32_t*)(sl + (size_t)mA * 256 + cn) = ll;
            split2(v2, v3, hh, ll);
            *(uint32_t*)(sh + (size_t)mB * 256 + cn) = hh;
            *(uint32_t*)(sl + (size_t)mB * 256 + cn) = ll;
        }
    }
}

__global__ __launch_bounds__(256, 1) void out_mma(const float* __restrict__ slope)
{
    extern __shared__ char sm[];
    const uint32_t sbase = smem_u32(sm);
    const int tid = threadIdx.x, wid = tid >> 5, lane = tid & 31;
    const int z = blockIdx.z;
    const int b = z / (Hh * NB), h = (z / NB) % Hh, c = z % NB, hk = h >> 1;
    const float s = slope[h];
    const int m0 = blockIdx.y * 128, n0 = blockIdx.x * 128;
    const int wm = (wid & 1) * 64, wn = (wid >> 1) * 32;
    const int t4 = lane & 3, tq = lane >> 2;
    const int fr = tid >> 3, fc = tid & 7;

    float acc[4][4][4] = {};

    {
        const __nv_bfloat16* Ah = g_qh + (size_t)(b * Ls + c * BLK + m0) * HD + h * Dd;
        const __nv_bfloat16* Al = g_ql + (size_t)(b * Ls + c * BLK + m0) * HD + h * Dd;
        const __nv_bfloat16* Bh = g_kvTh + (size_t)z * 65536 + (size_t)n0 * 256;
        const __nv_bfloat16* Bl = g_kvTl + (size_t)z * 65536 + (size_t)n0 * 256;
#define FILLO1(st, buf) do {                                                              \
    const uint32_t sb = sbase + (buf) * STAGE_B;                                          \
    const int k0 = (st) * 64;                                                             \
    fill_pair(sb + SA_H, sb + SA_L, Ah + k0, Al + k0, HD, fr, fc);                        \
    fill_pair(sb + SB_H, sb + SB_L, Bh + k0, Bl + k0, 256, fr, fc);                       \
} while (0)
        FILLO1(0, 0); CPCOMMIT();
        FILLO1(1, 1); CPCOMMIT();
        for (int st = 0; st < 4; st++) {
            CPWAIT1();
            __syncthreads();
            stage_mma(sbase + (st & 1) * STAGE_B, acc, wm, wn, lane);
            __syncthreads();
            if (st + 2 < 4) FILLO1(st + 2, st & 1);
            CPCOMMIT();
        }
#undef FILLO1
    }

#pragma unroll
    for (int mi = 0; mi < 4; mi++) {
        const int mA = m0 + wm + mi * 16 + tq;
        const float qd0 = expf(-s * (float)(mA + 1));
        const float qd1 = expf(-s * (float)(mA + 9));
#pragma unroll
        for (int ni = 0; ni < 4; ni++) {
            acc[mi][ni][0] *= qd0;
            acc[mi][ni][1] *= qd0;
            acc[mi][ni][2] *= qd1;
            acc[mi][ni][3] *= qd1;
        }
    }

    {
        const __nv_bfloat16* Ah = g_sch + (size_t)z * 65536 + (size_t)m0 * 256;
        const __nv_bfloat16* Al = g_scl + (size_t)z * 65536 + (size_t)m0 * 256;
        const __nv_bfloat16* Bh = g_vTh + ((size_t)(b * 8 + hk) * Dd + n0) * Ls + c * BLK;
        const __nv_bfloat16* Bl = g_vTl + ((size_t)(b * 8 + hk) * Dd + n0) * Ls + c * BLK;
#define FILLO2(st, buf) do {                                                              \
    const uint32_t sb = sbase + (buf) * STAGE_B;                                          \
    const int k0 = (st) * 64;                                                             \
    fill_pair(sb + SA_H, sb + SA_L, Ah + k0, Al + k0, 256, fr, fc);                       \
    fill_pair(sb + SB_H, sb + SB_L, Bh + k0, Bl + k0, Ls, fr, fc);                        \
} while (0)
        FILLO2(0, 0); CPCOMMIT();
        FILLO2(1, 1); CPCOMMIT();
        for (int st = 0; st < 4; st++) {
            CPWAIT1();
            __syncthreads();
            stage_mma(sbase + (st & 1) * STAGE_B, acc, wm, wn, lane);
            __syncthreads();
            if (st + 2 < 4) FILLO2(st + 2, st & 1);
            CPCOMMIT();
        }
#undef FILLO2
    }

    float* op = g_o + (size_t)(b * Ls + c * BLK) * HD + h * Dd;
#pragma unroll
    for (int mi = 0; mi < 4; mi++) {
        const int mA = m0 + wm + mi * 16 + tq, mB = mA + 8;
#pragma unroll
        for (int ni = 0; ni < 4; ni++) {
            const int cn = n0 + wn + ni * 8 + t4 * 2;
            *(float2*)(op + (size_t)mA * HD + cn) = make_float2(acc[mi][ni][0], acc[mi][ni][1]);
            *(float2*)(op + (size_t)mB * HD + cn) = make_float2(acc[mi][ni][2], acc[mi][ni][3]);
        }
    }
}

// ---------------- SimpleRMSNorm + bf16 hi/lo split output ----------------
__global__ __launch_bounds__(256) void rmsnorm_split_kernel()
{
    const int row = blockIdx.x;
    const float* p = g_o + (size_t)row * HD;
    __nv_bfloat16* oh = g_oh + (size_t)row * HD;
    __nv_bfloat16* ol = g_ol + (size_t)row * HD;
    const int tid = threadIdx.x;
    float ss = 0.f;
    for (int i = tid; i < HD; i += 256) {
        float v = p[i];
        ss += v * v;
    }
#pragma unroll
    for (int off = 16; off > 0; off >>= 1) ss += __shfl_xor_sync(0xffffffffu, ss, off);
    __shared__ float red[8];
    __shared__ float scale_s;
    if ((tid & 31) == 0) red[tid >> 5] = ss;
    __syncthreads();
    if (tid == 0) {
        float tot = 0.f;
#pragma unroll
        for (int w = 0; w < 8; w++) tot += red[w];
        scale_s = rsqrtf(tot / (float)HD + 1e-6f);
    }
    __syncthreads();
    const float sc = scale_s;
    for (int i = tid * 2; i < HD; i += 512) {
        float v0 = p[i] * sc, v1 = p[i + 1] * sc;
        uint32_t h, l;
        split2(v0, v1, h, l);
        *(uint32_t*)(oh + i) = h;
        *(uint32_t*)(ol + i) = l;
    }
}

// ---------------- launcher ----------------
extern "C" void kernel_launch(void* const* d_in, const int* in_sizes, int n_in,
                              void* d_out, int out_size)
{
    const float* x     = (const float*)d_in[0];
    const float* Wq    = (const float*)d_in[1];
    const float* Wk    = (const float*)d_in[2];
    const float* Wv    = (const float*)d_in[3];
    const float* Wo    = (const float*)d_in[4];
    const float* cqw   = (const float*)d_in[5];
    const float* cqb   = (const float*)d_in[6];
    const float* ckw   = (const float*)d_in[7];
    const float* ckb   = (const float*)d_in[8];
    const float* slope = (const float*)d_in[9];
    float* out = (float*)d_out;

    static cudaStream_t s2 = nullptr;
    static cudaEvent_t evF, ev1, ev2, evG, evK, evV, evP;
    if (!s2) {
        cudaStreamCreateWithFlags(&s2, cudaStreamNonBlocking);
        cudaEventCreateWithFlags(&evF, cudaEventDisableTiming);
        cudaEventCreateWithFlags(&ev1, cudaEventDisableTiming);
        cudaEventCreateWithFlags(&ev2, cudaEventDisableTiming);
        cudaEventCreateWithFlags(&evG, cudaEventDisableTiming);
        cudaEventCreateWithFlags(&evK, cudaEventDisableTiming);
        cudaEventCreateWithFlags(&evV, cudaEventDisableTiming);
        cudaEventCreateWithFlags(&evP, cudaEventDisableTiming);
    }

    float *qkvpre, *kf, *kT;
    __nv_bfloat16 *xh, *xl, *wqkvh, *wqkvl, *woh, *wol, *oh, *ol;
    __nv_bfloat16 *qh, *ql, *kh, *kl, *vth, *vtl;
    cudaGetSymbolAddress((void**)&qkvpre, g_qkvpre);
    cudaGetSymbolAddress((void**)&kf,     g_kf);
    cudaGetSymbolAddress((void**)&kT,     g_kT);
    cudaGetSymbolAddress((void**)&xh,     g_xh);
    cudaGetSymbolAddress((void**)&xl,     g_xl);
    cudaGetSymbolAddress((void**)&wqkvh,  g_wqkvh);
    cudaGetSymbolAddress((void**)&wqkvl,  g_wqkvl);
    cudaGetSymbolAddress((void**)&woh,    g_woh);
    cudaGetSymbolAddress((void**)&wol,    g_wol);
    cudaGetSymbolAddress((void**)&oh,     g_oh);
    cudaGetSymbolAddress((void**)&ol,     g_ol);
    cudaGetSymbolAddress((void**)&qh,     g_qh);
    cudaGetSymbolAddress((void**)&ql,     g_ql);
    cudaGetSymbolAddress((void**)&kh,     g_kh);
    cudaGetSymbolAddress((void**)&kl,     g_kl);
    cudaGetSymbolAddress((void**)&vth,    g_vTh);
    cudaGetSymbolAddress((void**)&vtl,    g_vTl);

    cudaFuncSetAttribute(hgemm2,    cudaFuncAttributeMaxDynamicSharedMemorySize, G2_SMEM);
    cudaFuncSetAttribute(kvloc_mma, cudaFuncAttributeMaxDynamicSharedMemorySize, HG_SMEM);
    cudaFuncSetAttribute(sc_mma,    cudaFuncAttributeMaxDynamicSharedMemorySize, HG_SMEM);
    cudaFuncSetAttribute(out_mma,   cudaFuncAttributeMaxDynamicSharedMemorySize, HG_SMEM);

    const int M = Bb * Ls;   // 4096

    // ---- fork: weight preparation on side stream ----
    cudaEventRecord(evF, 0);
    cudaStreamWaitEvent(s2, evF, 0);
    tsplit<<<dim3(HD / 32, HIDd / 32), 256, 0, s2>>>(Wq, wqkvh, wqkvl, HIDd, HD);
    tsplit<<<dim3(KD / 32, HIDd / 32), 256, 0, s2>>>(Wk, wqkvh + (size_t)HD * HIDd,
                                                     wqkvl + (size_t)HD * HIDd, HIDd, KD);
    tsplit<<<dim3(KD / 32, HIDd / 32), 256, 0, s2>>>(Wv, wqkvh + (size_t)(HD + KD) * HIDd,
                                                     wqkvl + (size_t)(HD + KD) * HIDd, HIDd, KD);
    cudaEventRecord(ev1, s2);
    tsplit<<<dim3(HIDd / 32, HD / 32), 256, 0, s2>>>(Wo, woh, wol, HD, HIDd);
    cudaEventRecord(ev2, s2);

    // ---- main: x split + fused QKV projection ----
    convsplit<<<(M * HIDd / 4 + 255) / 256, 256>>>(x, xh, xl, M * HIDd / 4);
    cudaStreamWaitEvent(0, ev1, 0);
    hgemm2<<<dim3(NQKV / 256, M / 128), 256, G2_SMEM>>>(xh, xl, wqkvh, wqkvl, qkvpre, M, NQKV, HIDd);
    cudaEventRecord(evG, 0);

    // ---- side stream: k path (conv_k -> kT) ----
    cudaStreamWaitEvent(s2, evG, 0);
    conv_silu_split<<<(M * KD / 2 + 255) / 256, 256, 0, s2>>>(qkvpre + HD, NQKV, ckw, ckb, kh, kl, kf, KD, M * KD / 2);
    cudaEventRecord(evK, s2);
    trans_f32<<<dim3(Ls / 32, Dd / 32, 16), 256, 0, s2>>>(kf, kT);

    // ---- main: v transpose + conv_q ----
    trans_split<<<dim3(Ls / 32, Dd / 32, 16), 256>>>(qkvpre, NQKV, HD + KD, vth, vtl);
    cudaEventRecord(evV, 0);
    conv_silu_split<<<(M * HD / 2 + 255) / 256, 256>>>(qkvpre, NQKV, cqw, cqb, qh, ql, nullptr, HD, M * HD / 2);

    // ---- side stream: kvloc + prefix (needs vT from main) ----
    cudaStreamWaitEvent(s2, evV, 0);
    kvloc_mma<<<dim3(2, 2, Bb * Hh * NB), 256, HG_SMEM, s2>>>(slope);
    kvprefix_split<<<(Bb * Hh * 32768) / 256, 256, 0, s2>>>(slope);
    cudaEventRecord(evP, s2);

    // ---- main: sc (needs k from side stream) ----
    cudaStreamWaitEvent(0, evK, 0);
    sc_mma<<<dim3(2, 2, Bb * Hh * NB), 256, HG_SMEM>>>(slope);

    cudaStreamWaitEvent(0, evP, 0);
    out_mma<<<dim3(2, 2, Bb * Hh * NB), 256, HG_SMEM>>>(slope);

    // norm + split + output projection
    rmsnorm_split_kernel<<<M, 256>>>();
    cudaStreamWaitEvent(0, ev2, 0);
    hgemm2<<<dim3(HIDd / 256, M / 128), 256, G2_SMEM>>>(oh, ol, woh, wol, out, M, HIDd, HD);
}

// round 10
// speedup vs baseline: 4.6011x; 1.3690x over previous
#include <cuda_runtime.h>
#include <cuda_fp16.h>
#include <cstdint>

#define Bb   2
#define Ls   2048
#define Hh   16
#define Dd   256
#define HD   4096   // H*D
#define KD   2048   // HKV*D
#define HIDd 2048
#define NB   8
#define BLK  256
#define NQKV 8192   // HD + KD + KD

// ---------------- scratch (static device memory; no allocs) ----------------
static __device__ __align__(128) float g_qkvpre[Bb * Ls * NQKV];
static __device__ __align__(128) float g_kf  [Bb * Ls * KD];
static __device__ __align__(128) float g_kv  [Bb * Hh * NB * Dd * Dd];
static __device__ __align__(128) float g_o   [Bb * Ls * HD];
static __device__ __align__(128) float g_kT  [16 * Dd * Ls];

static __device__ __align__(128) __half g_xh   [Bb * Ls * HIDd];
static __device__ __align__(128) __half g_xl   [Bb * Ls * HIDd];
static __device__ __align__(128) __half g_wqkvh[NQKV * HIDd];
static __device__ __align__(128) __half g_woh  [HIDd * HD];
static __device__ __align__(128) __half g_oh   [Bb * Ls * HD];
static __device__ __align__(128) __half g_ol   [Bb * Ls * HD];
static __device__ __align__(128) __half g_qh   [Bb * Ls * HD];
static __device__ __align__(128) __half g_ql   [Bb * Ls * HD];
static __device__ __align__(128) __half g_kh   [Bb * Ls * KD];
static __device__ __align__(128) __half g_vTh  [16 * Dd * Ls];
static __device__ __align__(128) __half g_vTl  [16 * Dd * Ls];
static __device__ __align__(128) __half g_kvTh [Bb * Hh * NB * Dd * Dd];
static __device__ __align__(128) __half g_sch  [Bb * Hh * NB * BLK * BLK];
static __device__ __align__(128) __half g_scl  [Bb * Hh * NB * BLK * BLK];

// =======================================================================
// helpers
// =======================================================================
__device__ __forceinline__ uint32_t smem_u32(const void* p) {
    uint32_t a;
    asm("{ .reg .u64 t; cvta.to.shared.u64 t, %1; cvt.u32.u64 %0, t; }" : "=r"(a) : "l"(p));
    return a;
}
__device__ __forceinline__ void split2h(float x0, float x1, uint32_t& hi, uint32_t& lo) {
    __half2 h = __floats2half2_rn(x0, x1);
    float r0 = x0 - __half2float(__low2half(h));
    float r1 = x1 - __half2float(__high2half(h));
    __half2 l = __floats2half2_rn(r0, r1);
    hi = *reinterpret_cast<uint32_t*>(&h);
    lo = *reinterpret_cast<uint32_t*>(&l);
}
__device__ __forceinline__ uint32_t round2h(float x0, float x1) {
    __half2 h = __floats2half2_rn(x0, x1);
    return *reinterpret_cast<uint32_t*>(&h);
}
#define CPA16(dst, src) asm volatile("cp.async.cg.shared.global [%0], [%1], 16;" :: "r"(dst), "l"(src))
#define CPCOMMIT()      asm volatile("cp.async.commit_group;" ::: "memory")
#define CPWAIT1()       asm volatile("cp.async.wait_group 1;" ::: "memory")
__device__ __forceinline__ void ldsm4(uint32_t a, uint32_t* r) {
    asm volatile("ldmatrix.sync.aligned.m8n8.x4.shared.b16 {%0,%1,%2,%3}, [%4];"
                 : "=r"(r[0]), "=r"(r[1]), "=r"(r[2]), "=r"(r[3]) : "r"(a));
}
__device__ __forceinline__ void mma16816(float* d, const uint32_t* a, const uint32_t* b) {
    asm volatile("mma.sync.aligned.m16n8k16.row.col.f32.f16.f16.f32 "
                 "{%0,%1,%2,%3}, {%4,%5,%6,%7}, {%8,%9}, {%0,%1,%2,%3};"
                 : "+f"(d[0]), "+f"(d[1]), "+f"(d[2]), "+f"(d[3])
                 : "r"(a[0]), "r"(a[1]), "r"(a[2]), "r"(a[3]), "r"(b[0]), "r"(b[1]));
}

// ---------- 128x128-tile layout (attention kernels): A hi/lo + B hi ----------
#define SA_H 0
#define SA_L 16384
#define SB_H 32768
#define STAGE_B 49152
#define HG_SMEM (2 * STAGE_B)

// one BK=64 stage: 2-term split (Ah*Bh + Al*Bh)
__device__ __forceinline__ void stage_mma(uint32_t sb, float acc[4][4][4],
                                          int wm, int wn, int lane)
{
    const int rA = lane & 15, kA = lane >> 4;
    const int rB = (lane & 7) | ((lane & 16) >> 1), kB = (lane >> 3) & 1;
    const int e = lane & 7;
    const uint32_t baseA = sb + (uint32_t)((wm + rA) * 128);
    const uint32_t baseB = sb + (uint32_t)((wn + rB) * 128);
#pragma unroll
    for (int kk = 0; kk < 4; kk++) {
        const uint32_t cA = (uint32_t)(((2 * kk + kA) ^ e) << 4);
        const uint32_t cB = (uint32_t)(((2 * kk + kB) ^ e) << 4);
        uint32_t ah[4][4], al[4][4], bh[2][4];
#pragma unroll
        for (int mi = 0; mi < 4; mi++) {
            ldsm4(baseA + SA_H + mi * 2048 + cA, ah[mi]);
            ldsm4(baseA + SA_L + mi * 2048 + cA, al[mi]);
        }
#pragma unroll
        for (int nj = 0; nj < 2; nj++)
            ldsm4(baseB + SB_H + nj * 2048 + cB, bh[nj]);
#pragma unroll
        for (int mi = 0; mi < 4; mi++)
#pragma unroll
            for (int ni = 0; ni < 4; ni++) {
                const uint32_t* bph = &bh[ni >> 1][(ni & 1) * 2];
                mma16816(acc[mi][ni], ah[mi], bph);
                mma16816(acc[mi][ni], al[mi], bph);
            }
    }
}

__device__ __forceinline__ void fill_pair(uint32_t sb_h, uint32_t sb_l,
                                          const __half* gh, const __half* gl,
                                          size_t stride, int fr, int fc)
{
#pragma unroll
    for (int i = 0; i < 4; i++) {
        int r = fr + 32 * i;
        uint32_t doff = (uint32_t)(r * 128 + ((fc ^ (r & 7)) << 4));
        size_t so = (size_t)r * stride + fc * 8;
        CPA16(sb_h + doff, gh + so);
        CPA16(sb_l + doff, gl + so);
    }
}

__device__ __forceinline__ void fill_one(uint32_t sb_h, const __half* gh,
                                         size_t stride, int fr, int fc)
{
#pragma unroll
    for (int i = 0; i < 4; i++) {
        int r = fr + 32 * i;
        uint32_t doff = (uint32_t)(r * 128 + ((fc ^ (r & 7)) << 4));
        CPA16(sb_h + doff, gh + (size_t)r * stride + fc * 8);
    }
}

// fp32 + per-column decay -> fp16 (hi only)
__device__ __forceinline__ void fill_f32_decay(char* smh, const float* g, size_t stride,
                                               int fr, int fc, float kd0, float ek)
{
    float kd[8];
    kd[0] = kd0;
#pragma unroll
    for (int j = 1; j < 8; j++) kd[j] = kd[j - 1] * ek;
#pragma unroll
    for (int i = 0; i < 4; i++) {
        int r = fr + 32 * i;
        uint32_t doff = (uint32_t)(r * 128 + ((fc ^ (r & 7)) << 4));
        const float* sp = g + (size_t)r * stride + fc * 8;
        float4 u = *(const float4*)sp;
        float4 w = *(const float4*)(sp + 4);
        uint4 hi;
        hi.x = round2h(u.x * kd[0], u.y * kd[1]);
        hi.y = round2h(u.z * kd[2], u.w * kd[3]);
        hi.z = round2h(w.x * kd[4], w.y * kd[5]);
        hi.w = round2h(w.z * kd[6], w.w * kd[7]);
        *(uint4*)(smh + doff) = hi;
    }
}

// =======================================================================
// hgemm2: 128(M) x 256(N), BK=64, 2-stage; A split, B fp16
// =======================================================================
#define G2_SA_H 0
#define G2_SA_L 16384
#define G2_SB_H 32768
#define G2_STAGE 65536
#define G2_SMEM (2 * G2_STAGE)

__global__ __launch_bounds__(256, 1) void hgemm2(const __half* __restrict__ Ah,
                                                 const __half* __restrict__ Al,
                                                 const __half* __restrict__ Bh,
                                                 float* __restrict__ C,
                                                 int M, int N, int K)
{
    extern __shared__ char sm[];
    const uint32_t sbase = smem_u32(sm);
    const int tid = threadIdx.x, wid = tid >> 5, lane = tid & 31;
    const int m0 = blockIdx.y * 128, n0 = blockIdx.x * 256;
    const int wm = (wid & 1) * 64, wn = (wid >> 1) * 64;
    const int t4 = lane & 3, tq = lane >> 2;
    const int fr = tid >> 3, fc = tid & 7;

    const int rA = lane & 15, kA = lane >> 4;
    const int rB = (lane & 7) | ((lane & 16) >> 1), kB = (lane >> 3) & 1;
    const int e = lane & 7;

    float acc[4][8][4];
#pragma unroll
    for (int a = 0; a < 4; a++)
#pragma unroll
        for (int b = 0; b < 8; b++)
#pragma unroll
            for (int c = 0; c < 4; c++) acc[a][b][c] = 0.f;

#define FILL2(s, buf) do {                                                                \
    const uint32_t sb = sbase + (buf) * G2_STAGE;                                         \
    const int k0 = (s) * 64;                                                              \
    _Pragma("unroll")                                                                     \
    for (int i = 0; i < 4; i++) {                                                         \
        int r = fr + 32 * i;                                                              \
        uint32_t doff = (uint32_t)(r * 128 + ((fc ^ (r & 7)) << 4));                      \
        size_t so = (size_t)(m0 + r) * K + k0 + fc * 8;                                   \
        CPA16(sb + G2_SA_H + doff, Ah + so);                                              \
        CPA16(sb + G2_SA_L + doff, Al + so);                                              \
    }                                                                                     \
    _Pragma("unroll")                                                                     \
    for (int i = 0; i < 8; i++) {                                                         \
        int r = fr + 32 * i;                                                              \
        uint32_t doff = (uint32_t)(r * 128 + ((fc ^ (r & 7)) << 4));                      \
        CPA16(sb + G2_SB_H + doff, Bh + (size_t)(n0 + r) * K + k0 + fc * 8);              \
    }                                                                                     \
} while (0)

    const int S = K / 64;
    FILL2(0, 0); CPCOMMIT();
    FILL2(1, 1); CPCOMMIT();

    for (int s = 0; s < S; s++) {
        CPWAIT1();
        __syncthreads();
        const uint32_t sb = sbase + (s & 1) * G2_STAGE;
        const uint32_t baseA = sb + (uint32_t)((wm + rA) * 128);
        const uint32_t baseB = sb + (uint32_t)((wn + rB) * 128);
#pragma unroll
        for (int kk = 0; kk < 4; kk++) {
            const uint32_t cA = (uint32_t)(((2 * kk + kA) ^ e) << 4);
            const uint32_t cB = (uint32_t)(((2 * kk + kB) ^ e) << 4);
            uint32_t ah[4][4], al[4][4], bh[4][4];
#pragma unroll
            for (int mi = 0; mi < 4; mi++) {
                ldsm4(baseA + G2_SA_H + mi * 2048 + cA, ah[mi]);
                ldsm4(baseA + G2_SA_L + mi * 2048 + cA, al[mi]);
            }
#pragma unroll
            for (int nj = 0; nj < 4; nj++)
                ldsm4(baseB + G2_SB_H + nj * 2048 + cB, bh[nj]);
#pragma unroll
            for (int mi = 0; mi < 4; mi++)
#pragma unroll
                for (int ni = 0; ni < 8; ni++) {
                    const uint32_t* bph = &bh[ni >> 1][(ni & 1) * 2];
                    mma16816(acc[mi][ni], ah[mi], bph);
                    mma16816(acc[mi][ni], al[mi], bph);
                }
        }
        __syncthreads();
        if (s + 2 < S) FILL2(s + 2, s & 1);
        CPCOMMIT();
    }
#undef FILL2

#pragma unroll
    for (int mi = 0; mi < 4; mi++) {
        const int m = m0 + wm + mi * 16 + tq;
#pragma unroll
        for (int ni = 0; ni < 8; ni++) {
            const int n = n0 + wn + ni * 8 + t4 * 2;
            *(float2*)(C + (size_t)m * N + n)       = make_float2(acc[mi][ni][0], acc[mi][ni][1]);
            *(float2*)(C + (size_t)(m + 8) * N + n) = make_float2(acc[mi][ni][2], acc[mi][ni][3]);
        }
    }
}

// =======================================================================
// convert kernels
// =======================================================================
__global__ __launch_bounds__(256) void convsplit(const float* __restrict__ in,
                                                 __half* __restrict__ hi,
                                                 __half* __restrict__ lo, int n4)
{
    int i = blockIdx.x * 256 + threadIdx.x;
    if (i >= n4) return;
    float4 v = ((const float4*)in)[i];
    uint2 h, l;
    split2h(v.x, v.y, h.x, l.x);
    split2h(v.z, v.w, h.y, l.y);
    ((uint2*)hi)[i] = h;
    ((uint2*)lo)[i] = l;
}

// W[K][N] fp32 -> Wt[N][K] fp16 (hi only)
__global__ __launch_bounds__(256) void tsplit(const float* __restrict__ W,
                                              __half* __restrict__ th,
                                              int Kd, int Nd)
{
    __shared__ float t[32][33];
    const int bxn = blockIdx.x * 32;
    const int byk = blockIdx.y * 32;
    const int x = threadIdx.x & 31, y = threadIdx.x >> 5;
#pragma unroll
    for (int j = 0; j < 4; j++)
        t[y + 8 * j][x] = W[(size_t)(byk + y + 8 * j) * Nd + bxn + x];
    __syncthreads();
    const int n = bxn + x;
    uint2 h;
    h.x = round2h(t[y * 4 + 0][x], t[y * 4 + 1][x]);
    h.y = round2h(t[y * 4 + 2][x], t[y * 4 + 3][x]);
    ((uint2*)th)[((size_t)n * Kd + byk + y * 4) >> 2] = h;
}

__global__ __launch_bounds__(256) void trans_f32(const float* __restrict__ in,
                                                 float* __restrict__ out)
{
    __shared__ float t[32][33];
    const int bk = blockIdx.z;
    const int b = bk >> 3, hk = bk & 7;
    const int l0 = blockIdx.x * 32, d0 = blockIdx.y * 32;
    const int x = threadIdx.x & 31, y = threadIdx.x >> 5;
#pragma unroll
    for (int j = 0; j < 4; j++)
        t[y + 8 * j][x] = in[(size_t)(b * Ls + l0 + y + 8 * j) * KD + hk * Dd + d0 + x];
    __syncthreads();
#pragma unroll
    for (int j = 0; j < 4; j++) {
        int d = d0 + y + 8 * j;
        out[((size_t)bk * Dd + d) * Ls + l0 + x] = t[x][y + 8 * j];
    }
}

// transpose strided fp32 -> fp16 hi/lo [b*8+hk][d][l]
__global__ __launch_bounds__(256) void trans_split(const float* __restrict__ in,
                                                   int instride, int colbase,
                                                   __half* __restrict__ oth,
                                                   __half* __restrict__ otl)
{
    __shared__ float t[32][33];
    const int bk = blockIdx.z;
    const int b = bk >> 3, hk = bk & 7;
    const int l0 = blockIdx.x * 32, d0 = blockIdx.y * 32;
    const int x = threadIdx.x & 31, y = threadIdx.x >> 5;
#pragma unroll
    for (int j = 0; j < 4; j++)
        t[y + 8 * j][x] = in[(size_t)(b * Ls + l0 + y + 8 * j) * instride + colbase + hk * Dd + d0 + x];
    __syncthreads();
    const int x2 = threadIdx.x & 15, yy = threadIdx.x >> 4;
#pragma unroll
    for (int j = 0; j < 2; j++) {
        int d = d0 + yy + 16 * j;
        uint32_t h, l;
        split2h(t[x2 * 2][yy + 16 * j], t[x2 * 2 + 1][yy + 16 * j], h, l);
        size_t off = (((size_t)bk * Dd + d) * Ls + l0 + x2 * 2) >> 1;
        ((uint32_t*)oth)[off] = h;
        ((uint32_t*)otl)[off] = l;
    }
}

// conv + silu; hi always, lo/f32 optional
__global__ __launch_bounds__(256) void conv_silu_split(const float* __restrict__ in,
                                                       int instride,
                                                       const float* __restrict__ w,
                                                       const float* __restrict__ bias,
                                                       __half* __restrict__ oh,
                                                       __half* __restrict__ ol,
                                                       float* __restrict__ of32,
                                                       int C, int npairs)
{
    int p = blockIdx.x * 256 + threadIdx.x;
    if (p >= npairs) return;
    const int Ch = C >> 1;
    int row = p / Ch;
    int c = (p - row * Ch) * 2;
    int l = row & (Ls - 1);
    const float* ip = in + (size_t)row * instride + c;
    float a0 = bias[c], a1 = bias[c + 1];
#pragma unroll
    for (int t = 0; t < 4; t++) {
        int ls = l + t - 3;
        if (ls >= 0) {
            a0 += w[c * 4 + t]       * ip[(ptrdiff_t)(t - 3) * instride];
            a1 += w[(c + 1) * 4 + t] * ip[(ptrdiff_t)(t - 3) * instride + 1];
        }
    }
    a0 = a0 / (1.f + expf(-a0));
    a1 = a1 / (1.f + expf(-a1));
    size_t oidx = (size_t)row * C + c;
    if (of32) { of32[oidx] = a0; of32[oidx + 1] = a1; }
    uint32_t h, lo;
    split2h(a0, a1, h, lo);
    ((uint32_t*)oh)[oidx >> 1] = h;
    if (ol) ((uint32_t*)ol)[oidx >> 1] = lo;
}

// =======================================================================
// attention MMA kernels
// =======================================================================
__global__ __launch_bounds__(256, 1) void kvloc_mma(const float* __restrict__ slope)
{
    extern __shared__ char sm[];
    const uint32_t sbase = smem_u32(sm);
    const int tid = threadIdx.x, wid = tid >> 5, lane = tid & 31;
    const int z = blockIdx.z;
    const int b = z / (Hh * NB), h = (z / NB) % Hh, c = z % NB, hk = h >> 1;
    const float s = slope[h];
    const int m0 = blockIdx.y * 128, n0 = blockIdx.x * 128;
    const int wm = (wid & 1) * 64, wn = (wid >> 1) * 32;
    const int t4 = lane & 3, tq = lane >> 2;
    const int fr = tid >> 3, fc = tid & 7;

    const __half* Avh = g_vTh + ((size_t)(b * 8 + hk) * Dd + m0) * Ls + c * BLK;
    const __half* Avl = g_vTl + ((size_t)(b * 8 + hk) * Dd + m0) * Ls + c * BLK;
    const float* BkT = g_kT + ((size_t)(b * 8 + hk) * Dd + n0) * Ls + c * BLK;
    const float ek = expf(s);

    float acc[4][4][4] = {};

#define FILLKV(st, buf) do {                                                              \
    const uint32_t sb = sbase + (buf) * STAGE_B;                                          \
    char* smb = sm + (buf) * STAGE_B;                                                     \
    const int k0 = (st) * 64;                                                             \
    fill_pair(sb + SA_H, sb + SA_L, Avh + k0, Avl + k0, Ls, fr, fc);                      \
    float kd0 = expf(-s * (float)(255 - (k0 + fc * 8)));                                  \
    fill_f32_decay(smb + SB_H, BkT + k0, Ls, fr, fc, kd0, ek);                            \
} while (0)

    FILLKV(0, 0); CPCOMMIT();
    FILLKV(1, 1); CPCOMMIT();
    for (int st = 0; st < 4; st++) {
        CPWAIT1();
        __syncthreads();
        stage_mma(sbase + (st & 1) * STAGE_B, acc, wm, wn, lane);
        __syncthreads();
        if (st + 2 < 4) FILLKV(st + 2, st & 1);
        CPCOMMIT();
    }
#undef FILLKV

    float* op = g_kv + (size_t)z * 65536;
#pragma unroll
    for (int mi = 0; mi < 4; mi++) {
        const int mA = m0 + wm + mi * 16 + tq, mB = mA + 8;
#pragma unroll
        for (int ni = 0; ni < 4; ni++) {
            const int cn = n0 + wn + ni * 8 + t4 * 2;
            *(float2*)(op + (size_t)mA * 256 + cn) = make_float2(acc[mi][ni][0], acc[mi][ni][1]);
            *(float2*)(op + (size_t)mB * 256 + cn) = make_float2(acc[mi][ni][2], acc[mi][ni][3]);
        }
    }
}

// exclusive decay prefix over chunks (fp32 in, fp16 hi out)
__global__ __launch_bounds__(256) void kvprefix_split(const float* __restrict__ slope)
{
    const int pidx = blockIdx.x * 256 + threadIdx.x;
    const int bh = pidx >> 15;
    const int off = (pidx & 32767) * 2;
    const int h = bh % Hh;
    const float bdec = expf(-slope[h] * (float)BLK);
    const float* p = g_kv + (size_t)bh * NB * 65536 + off;
    __half* oh = g_kvTh + (size_t)bh * NB * 65536 + off;
    float a0 = 0.f, a1 = 0.f;
#pragma unroll
    for (int c = 0; c < NB; c++) {
        float2 loc = *(const float2*)(p + (size_t)c * 65536);
        *(uint32_t*)(oh + (size_t)c * 65536) = round2h(a0, a1);
        a0 = a0 * bdec + loc.x;
        a1 = a1 * bdec + loc.y;
    }
}

__global__ __launch_bounds__(256, 1) void sc_mma(const float* __restrict__ slope)
{
    extern __shared__ char sm[];
    const uint32_t sbase = smem_u32(sm);
    const int tid = threadIdx.x, wid = tid >> 5, lane = tid & 31;
    const int z = blockIdx.z;
    const int b = z / (Hh * NB), h = (z / NB) % Hh, c = z % NB, hk = h >> 1;
    const float s = slope[h];
    const int m0 = blockIdx.y * 128, n0 = blockIdx.x * 128;
    const int wm = (wid & 1) * 64, wn = (wid >> 1) * 32;
    const int t4 = lane & 3, tq = lane >> 2;
    const int fr = tid >> 3, fc = tid & 7;

    const __half* Ah = g_qh + (size_t)(b * Ls + c * BLK + m0) * HD + h * Dd;
    const __half* Al = g_ql + (size_t)(b * Ls + c * BLK + m0) * HD + h * Dd;
    const __half* Bh = g_kh + (size_t)(b * Ls + c * BLK + n0) * KD + hk * Dd;

    float acc[4][4][4] = {};

#define FILLSC(st, buf) do {                                                              \
    const uint32_t sb = sbase + (buf) * STAGE_B;                                          \
    const int k0 = (st) * 64;                                                             \
    fill_pair(sb + SA_H, sb + SA_L, Ah + k0, Al + k0, HD, fr, fc);                        \
    fill_one(sb + SB_H, Bh + k0, KD, fr, fc);                                             \
} while (0)

    FILLSC(0, 0); CPCOMMIT();
    FILLSC(1, 1); CPCOMMIT();
    for (int st = 0; st < 4; st++) {
        CPWAIT1();
        __syncthreads();
        stage_mma(sbase + (st & 1) * STAGE_B, acc, wm, wn, lane);
        __syncthreads();
        if (st + 2 < 4) FILLSC(st + 2, st & 1);
        CPCOMMIT();
    }
#undef FILLSC

    __half* sh = g_sch + (size_t)z * 65536;
    __half* sl = g_scl + (size_t)z * 65536;
#pragma unroll
    for (int mi = 0; mi < 4; mi++) {
        const int mA = m0 + wm + mi * 16 + tq, mB = mA + 8;
#pragma unroll
        for (int ni = 0; ni < 4; ni++) {
            const int cn = n0 + wn + ni * 8 + t4 * 2;
            float v0 = (mA >= cn)     ? acc[mi][ni][0] * expf(-s * (float)(mA - cn))     : 0.f;
            float v1 = (mA >= cn + 1) ? acc[mi][ni][1] * expf(-s * (float)(mA - cn - 1)) : 0.f;
            float v2 = (mB >= cn)     ? acc[mi][ni][2] * expf(-s * (float)(mB - cn))     : 0.f;
            float v3 = (mB >= cn + 1) ? acc[mi][ni][3] * expf(-s * (float)(mB - cn - 1)) : 0.f;
            uint32_t hh, ll;
            split2h(v0, v1, hh, ll);
            *(uint32_t*)(sh + (size_t)mA * 256 + cn) = hh;
            *(uint32_t*)(sl + (size_t)mA * 256 + cn) = ll;
            split2h(v2, v3, hh, ll);
            *(uint32_t*)(sh + (size_t)mB * 256 + cn) = hh;
            *(uint32_t*)(sl + (size_t)mB * 256 + cn) = ll;
        }
    }
}

__global__ __launch_bounds__(256, 1) void out_mma(const float* __restrict__ slope)
{
    extern __shared__ char sm[];
    const uint32_t sbase = smem_u32(sm);
    const int tid = threadIdx.x, wid = tid >> 5, lane = tid & 31;
    const int z = blockIdx.z;
    const int b = z / (Hh * NB), h = (z / NB) % Hh, c = z % NB, hk = h >> 1;
    const float s = slope[h];
    const int m0 = blockIdx.y * 128, n0 = blockIdx.x * 128;
    const int wm = (wid & 1) * 64, wn = (wid >> 1) * 32;
    const int t4 = lane & 3, tq = lane >> 2;
    const int fr = tid >> 3, fc = tid & 7;

    float acc[4][4][4] = {};

    {
        const __half* Ah = g_qh + (size_t)(b * Ls + c * BLK + m0) * HD + h * Dd;
        const __half* Al = g_ql + (size_t)(b * Ls + c * BLK + m0) * HD + h * Dd;
        const __half* Bh = g_kvTh + (size_t)z * 65536 + (size_t)n0 * 256;
#define FILLO1(st, buf) do {                                                              \
    const uint32_t sb = sbase + (buf) * STAGE_B;                                          \
    const int k0 = (st) * 64;                                                             \
    fill_pair(sb + SA_H, sb + SA_L, Ah + k0, Al + k0, HD, fr, fc);                        \
    fill_one(sb + SB_H, Bh + k0, 256, fr, fc);                                            \
} while (0)
        FILLO1(0, 0); CPCOMMIT();
        FILLO1(1, 1); CPCOMMIT();
        for (int st = 0; st < 4; st++) {
            CPWAIT1();
            __syncthreads();
            stage_mma(sbase + (st & 1) * STAGE_B, acc, wm, wn, lane);
            __syncthreads();
            if (st + 2 < 4) FILLO1(st + 2, st & 1);
            CPCOMMIT();
        }
#undef FILLO1
    }

#pragma unroll
    for (int mi = 0; mi < 4; mi++) {
        const int mA = m0 + wm + mi * 16 + tq;
        const float qd0 = expf(-s * (float)(mA + 1));
        const float qd1 = expf(-s * (float)(mA + 9));
#pragma unroll
        for (int ni = 0; ni < 4; ni++) {
            acc[mi][ni][0] *= qd0;
            acc[mi][ni][1] *= qd0;
            acc[mi][ni][2] *= qd1;
            acc[mi][ni][3] *= qd1;
        }
    }

    {
        const __half* Ah = g_sch + (size_t)z * 65536 + (size_t)m0 * 256;
        const __half* Al = g_scl + (size_t)z * 65536 + (size_t)m0 * 256;
        const __half* Bh = g_vTh + ((size_t)(b * 8 + hk) * Dd + n0) * Ls + c * BLK;
#define FILLO2(st, buf) do {                                                              \
    const uint32_t sb = sbase + (buf) * STAGE_B;                                          \
    const int k0 = (st) * 64;                                                             \
    fill_pair(sb + SA_H, sb + SA_L, Ah + k0, Al + k0, 256, fr, fc);                       \
    fill_one(sb + SB_H, Bh + k0, Ls, fr, fc);                                             \
} while (0)
        FILLO2(0, 0); CPCOMMIT();
        FILLO2(1, 1); CPCOMMIT();
        for (int st = 0; st < 4; st++) {
            CPWAIT1();
            __syncthreads();
            stage_mma(sbase + (st & 1) * STAGE_B, acc, wm, wn, lane);
            __syncthreads();
            if (st + 2 < 4) FILLO2(st + 2, st & 1);
            CPCOMMIT();
        }
#undef FILLO2
    }

    float* op = g_o + (size_t)(b * Ls + c * BLK) * HD + h * Dd;
#pragma unroll
    for (int mi = 0; mi < 4; mi++) {
        const int mA = m0 + wm + mi * 16 + tq, mB = mA + 8;
#pragma unroll
        for (int ni = 0; ni < 4; ni++) {
            const int cn = n0 + wn + ni * 8 + t4 * 2;
            *(float2*)(op + (size_t)mA * HD + cn) = make_float2(acc[mi][ni][0], acc[mi][ni][1]);
            *(float2*)(op + (size_t)mB * HD + cn) = make_float2(acc[mi][ni][2], acc[mi][ni][3]);
        }
    }
}

// ---------------- SimpleRMSNorm + fp16 hi/lo split output ----------------
__global__ __launch_bounds__(256) void rmsnorm_split_kernel()
{
    const int row = blockIdx.x;
    const float* p = g_o + (size_t)row * HD;
    __half* oh = g_oh + (size_t)row * HD;
    __half* ol = g_ol + (size_t)row * HD;
    const int tid = threadIdx.x;
    float ss = 0.f;
    for (int i = tid; i < HD; i += 256) {
        float v = p[i];
        ss += v * v;
    }
#pragma unroll
    for (int off = 16; off > 0; off >>= 1) ss += __shfl_xor_sync(0xffffffffu, ss, off);
    __shared__ float red[8];
    __shared__ float scale_s;
    if ((tid & 31) == 0) red[tid >> 5] = ss;
    __syncthreads();
    if (tid == 0) {
        float tot = 0.f;
#pragma unroll
        for (int w = 0; w < 8; w++) tot += red[w];
        scale_s = rsqrtf(tot / (float)HD + 1e-6f);
    }
    __syncthreads();
    const float sc = scale_s;
    for (int i = tid * 2; i < HD; i += 512) {
        uint32_t h, l;
        split2h(p[i] * sc, p[i + 1] * sc, h, l);
        *(uint32_t*)(oh + i) = h;
        *(uint32_t*)(ol + i) = l;
    }
}

// ---------------- launcher ----------------
extern "C" void kernel_launch(void* const* d_in, const int* in_sizes, int n_in,
                              void* d_out, int out_size)
{
    const float* x     = (const float*)d_in[0];
    const float* Wq    = (const float*)d_in[1];
    const float* Wk    = (const float*)d_in[2];
    const float* Wv    = (const float*)d_in[3];
    const float* Wo    = (const float*)d_in[4];
    const float* cqw   = (const float*)d_in[5];
    const float* cqb   = (const float*)d_in[6];
    const float* ckw   = (const float*)d_in[7];
    const float* ckb   = (const float*)d_in[8];
    const float* slope = (const float*)d_in[9];
    float* out = (float*)d_out;

    static cudaStream_t s2 = nullptr;
    static cudaEvent_t evF, ev1, ev2, evG, evK, evV, evP;
    if (!s2) {
        cudaStreamCreateWithFlags(&s2, cudaStreamNonBlocking);
        cudaEventCreateWithFlags(&evF, cudaEventDisableTiming);
        cudaEventCreateWithFlags(&ev1, cudaEventDisableTiming);
        cudaEventCreateWithFlags(&ev2, cudaEventDisableTiming);
        cudaEventCreateWithFlags(&evG, cudaEventDisableTiming);
        cudaEventCreateWithFlags(&evK, cudaEventDisableTiming);
        cudaEventCreateWithFlags(&evV, cudaEventDisableTiming);
        cudaEventCreateWithFlags(&evP, cudaEventDisableTiming);
    }

    float *qkvpre, *kf, *kT;
    __half *xh, *xl, *wqkvh, *woh, *oh, *ol, *qh, *ql, *kh, *vth, *vtl;
    cudaGetSymbolAddress((void**)&qkvpre, g_qkvpre);
    cudaGetSymbolAddress((void**)&kf,     g_kf);
    cudaGetSymbolAddress((void**)&kT,     g_kT);
    cudaGetSymbolAddress((void**)&xh,     g_xh);
    cudaGetSymbolAddress((void**)&xl,     g_xl);
    cudaGetSymbolAddress((void**)&wqkvh,  g_wqkvh);
    cudaGetSymbolAddress((void**)&woh,    g_woh);
    cudaGetSymbolAddress((void**)&oh,     g_oh);
    cudaGetSymbolAddress((void**)&ol,     g_ol);
    cudaGetSymbolAddress((void**)&qh,     g_qh);
    cudaGetSymbolAddress((void**)&ql,     g_ql);
    cudaGetSymbolAddress((void**)&kh,     g_kh);
    cudaGetSymbolAddress((void**)&vth,    g_vTh);
    cudaGetSymbolAddress((void**)&vtl,    g_vTl);

    cudaFuncSetAttribute(hgemm2,    cudaFuncAttributeMaxDynamicSharedMemorySize, G2_SMEM);
    cudaFuncSetAttribute(kvloc_mma, cudaFuncAttributeMaxDynamicSharedMemorySize, HG_SMEM);
    cudaFuncSetAttribute(sc_mma,    cudaFuncAttributeMaxDynamicSharedMemorySize, HG_SMEM);
    cudaFuncSetAttribute(out_mma,   cudaFuncAttributeMaxDynamicSharedMemorySize, HG_SMEM);

    const int M = Bb * Ls;   // 4096

    // ---- fork: weight preparation on side stream ----
    cudaEventRecord(evF, 0);
    cudaStreamWaitEvent(s2, evF, 0);
    tsplit<<<dim3(HD / 32, HIDd / 32), 256, 0, s2>>>(Wq, wqkvh, HIDd, HD);
    tsplit<<<dim3(KD / 32, HIDd / 32), 256, 0, s2>>>(Wk, wqkvh + (size_t)HD * HIDd, HIDd, KD);
    tsplit<<<dim3(KD / 32, HIDd / 32), 256, 0, s2>>>(Wv, wqkvh + (size_t)(HD + KD) * HIDd, HIDd, KD);
    cudaEventRecord(ev1, s2);
    tsplit<<<dim3(HIDd / 32, HD / 32), 256, 0, s2>>>(Wo, woh, HD, HIDd);
    cudaEventRecord(ev2, s2);

    // ---- main: x split + fused QKV projection ----
    convsplit<<<(M * HIDd / 4 + 255) / 256, 256>>>(x, xh, xl, M * HIDd / 4);
    cudaStreamWaitEvent(0, ev1, 0);
    hgemm2<<<dim3(NQKV / 256, M / 128), 256, G2_SMEM>>>(xh, xl, wqkvh, qkvpre, M, NQKV, HIDd);
    cudaEventRecord(evG, 0);

    // ---- side stream: k path (conv_k -> kT) ----
    cudaStreamWaitEvent(s2, evG, 0);
    conv_silu_split<<<(M * KD / 2 + 255) / 256, 256, 0, s2>>>(qkvpre + HD, NQKV, ckw, ckb, kh, nullptr, kf, KD, M * KD / 2);
    cudaEventRecord(evK, s2);
    trans_f32<<<dim3(Ls / 32, Dd / 32, 16), 256, 0, s2>>>(kf, kT);

    // ---- main: v transpose + conv_q ----
    trans_split<<<dim3(Ls / 32, Dd / 32, 16), 256>>>(qkvpre, NQKV, HD + KD, vth, vtl);
    cudaEventRecord(evV, 0);
    conv_silu_split<<<(M * HD / 2 + 255) / 256, 256>>>(qkvpre, NQKV, cqw, cqb, qh, ql, nullptr, HD, M * HD / 2);

    // ---- side stream: kvloc + prefix (needs vT from main) ----
    cudaStreamWaitEvent(s2, evV, 0);
    kvloc_mma<<<dim3(2, 2, Bb * Hh * NB), 256, HG_SMEM, s2>>>(slope);
    kvprefix_split<<<(Bb * Hh * 32768) / 256, 256, 0, s2>>>(slope);
    cudaEventRecord(evP, s2);

    // ---- main: sc (needs k from side stream) ----
    cudaStreamWaitEvent(0, evK, 0);
    sc_mma<<<dim3(2, 2, Bb * Hh * NB), 256, HG_SMEM>>>(slope);

    cudaStreamWaitEvent(0, evP, 0);
    out_mma<<<dim3(2, 2, Bb * Hh * NB), 256, HG_SMEM>>>(slope);

    // norm + split + output projection
    rmsnorm_split_kernel<<<M, 256>>>();
    cudaStreamWaitEvent(0, ev2, 0);
    hgemm2<<<dim3(HIDd / 256, M / 128), 256, G2_SMEM>>>(oh, ol, woh, out, M, HIDd, HD);
}